// round 3
// baseline (speedup 1.0000x reference)
#include <cuda_runtime.h>
#include <cuda_bf16.h>
#include <math.h>

#define NNODE 100000
#define NP 3
#define NE 800000
#define INF 128
#define NH 4
#define ND 32
#define HD 128
#define HID 64
#define PN (NP*NNODE)
#define PE (NP*NE)
#define NEG_SLOPE 0.2f

// scan config
#define SCAN_ITEMS 1024
#define NB ((PN + SCAN_ITEMS - 1) / SCAN_ITEMS)   // 293

// ---------------- device scratch (static, no allocations) ----------------
__device__ __align__(16) float g_feat[(size_t)NP * NNODE * HD];
__device__ __align__(16) float g_z[(size_t)NP * NNODE * HD];
__device__ __align__(16) float g_el[PN * NH];
__device__ __align__(16) float g_er[PN * NH];
__device__ int   g_count[PN];
__device__ int   g_cursor[PN];
__device__ int   g_off[PN];
__device__ int   g_bsums[512];
__device__ int   g_esrc[PE];                        // src ids grouped by (p,dst)
__device__ float g_wsum[NP];

// ---------------- K0: init ----------------
__global__ void k_init() {
    int i = blockIdx.x * blockDim.x + threadIdx.x;
    if (i < PN) { g_count[i] = 0; g_cursor[i] = 0; }
    if (i < NP) g_wsum[i] = 0.f;
}

// ---------------- K1: feat = h @ W_p, fused el/er ----------------
// block: 256 threads, 64 rows x 128 cols. thread: 4 rows x 8 cols.
// K processed in 4 chunks of 32 so static smem stays at 25.6 KB.
__global__ void __launch_bounds__(256) k_gemm(const float* __restrict__ h,
                                              const float* __restrict__ W,
                                              const float* __restrict__ attn_l,
                                              const float* __restrict__ attn_r) {
    __shared__ float Ws[32 * 128];   // one K-chunk of W: [32][128]
    __shared__ float hs[64 * 36];    // h tile: [64][32] padded to 36

    const int p = blockIdx.y;
    const int row0 = blockIdx.x * 64;
    const float* Wp = W + (size_t)p * INF * HD;

    const int cg = threadIdx.x & 15;   // col group
    const int rg = threadIdx.x >> 4;   // row group (x4 rows)
    const int c0 = cg * 8;

    float acc[4][8];
#pragma unroll
    for (int r = 0; r < 4; r++)
#pragma unroll
        for (int j = 0; j < 8; j++) acc[r][j] = 0.f;

    for (int kc = 0; kc < 4; kc++) {
        {
            const float4* src = (const float4*)(Wp + kc * 32 * 128);
            for (int i = threadIdx.x; i < 1024; i += 256)
                ((float4*)Ws)[i] = src[i];
        }
        for (int i = threadIdx.x; i < 512; i += 256) {
            int r = i >> 3;        // row 0..63
            int q = i & 7;         // float4 within 32-col chunk
            float4 v = make_float4(0.f, 0.f, 0.f, 0.f);
            if (row0 + r < NNODE)
                v = *(const float4*)(h + (size_t)(row0 + r) * INF + kc * 32 + q * 4);
            *(float4*)&hs[r * 36 + q * 4] = v;
        }
        __syncthreads();

#pragma unroll
        for (int k = 0; k < 32; k += 4) {
            float4 hv[4];
#pragma unroll
            for (int r = 0; r < 4; r++)
                hv[r] = *(const float4*)&hs[(rg * 4 + r) * 36 + k];
#pragma unroll
            for (int kk = 0; kk < 4; kk++) {
                float4 wa = *(const float4*)&Ws[(k + kk) * 128 + c0];
                float4 wb = *(const float4*)&Ws[(k + kk) * 128 + c0 + 4];
#pragma unroll
                for (int r = 0; r < 4; r++) {
                    float hr = (kk == 0) ? hv[r].x : (kk == 1) ? hv[r].y
                             : (kk == 2) ? hv[r].z : hv[r].w;
                    acc[r][0] += hr * wa.x; acc[r][1] += hr * wa.y;
                    acc[r][2] += hr * wa.z; acc[r][3] += hr * wa.w;
                    acc[r][4] += hr * wb.x; acc[r][5] += hr * wb.y;
                    acc[r][6] += hr * wb.z; acc[r][7] += hr * wb.w;
                }
            }
        }
        __syncthreads();
    }

    // epilogue: store feat, reduce el/er per head
    const float* alp = attn_l + p * HD;
    const float* arp = attn_r + p * HD;
    const int head = c0 >> 5;
#pragma unroll
    for (int r = 0; r < 4; r++) {
        int row = row0 + rg * 4 + r;
        bool ok = row < NNODE;
        if (ok) {
            float* fp = &g_feat[((size_t)p * NNODE + row) * HD + c0];
            *(float4*)fp       = make_float4(acc[r][0], acc[r][1], acc[r][2], acc[r][3]);
            *(float4*)(fp + 4) = make_float4(acc[r][4], acc[r][5], acc[r][6], acc[r][7]);
        }
        float vl = 0.f, vr = 0.f;
#pragma unroll
        for (int j = 0; j < 8; j++) {
            vl += acc[r][j] * alp[c0 + j];
            vr += acc[r][j] * arp[c0 + j];
        }
        vl += __shfl_xor_sync(0xffffffffu, vl, 1);
        vl += __shfl_xor_sync(0xffffffffu, vl, 2);
        vr += __shfl_xor_sync(0xffffffffu, vr, 1);
        vr += __shfl_xor_sync(0xffffffffu, vr, 2);
        if (ok && (cg & 3) == 0) {
            g_el[(p * NNODE + row) * NH + head] = vl;
            g_er[(p * NNODE + row) * NH + head] = vr;
        }
    }
}

// ---------------- K2: count in-degree (edges are int32!) ----------------
__global__ void k_count(const int* __restrict__ edge_dst) {
    int i = blockIdx.x * blockDim.x + threadIdx.x;
    if (i >= PE) return;
    int p = i / NE;
    int dst = edge_dst[i];
    atomicAdd(&g_count[p * NNODE + dst], 1);
}

// ---------------- scan (3 kernels) ----------------
__global__ void k_scan_blocks() {
    __shared__ int s[256];
    int base = blockIdx.x * SCAN_ITEMS;
    int t = threadIdx.x;
    int v = 0;
#pragma unroll
    for (int i = 0; i < 4; i++) {
        int idx = base + t * 4 + i;
        if (idx < PN) v += g_count[idx];
    }
    s[t] = v; __syncthreads();
    for (int o = 128; o > 0; o >>= 1) {
        if (t < o) s[t] += s[t + o];
        __syncthreads();
    }
    if (t == 0) g_bsums[blockIdx.x] = s[0];
}

__global__ void k_scan_bsums() {
    __shared__ int s[512];
    int t = threadIdx.x;
    int v = (t < NB) ? g_bsums[t] : 0;
    s[t] = v; __syncthreads();
    for (int o = 1; o < 512; o <<= 1) {
        int x = (t >= o) ? s[t - o] : 0;
        __syncthreads();
        s[t] += x;
        __syncthreads();
    }
    if (t < NB) g_bsums[t] = s[t] - v;  // exclusive
}

__global__ void k_scan_final() {
    __shared__ int s[256];
    int base = blockIdx.x * SCAN_ITEMS;
    int t = threadIdx.x;
    int loc[4]; int sum = 0;
#pragma unroll
    for (int i = 0; i < 4; i++) {
        int idx = base + t * 4 + i;
        loc[i] = (idx < PN) ? g_count[idx] : 0;
        sum += loc[i];
    }
    s[t] = sum; __syncthreads();
    for (int o = 1; o < 256; o <<= 1) {
        int x = (t >= o) ? s[t - o] : 0;
        __syncthreads();
        s[t] += x;
        __syncthreads();
    }
    int ex = s[t] - sum + g_bsums[blockIdx.x];
#pragma unroll
    for (int i = 0; i < 4; i++) {
        int idx = base + t * 4 + i;
        if (idx < PN) { g_off[idx] = ex; ex += loc[i]; }
    }
}

// ---------------- K3: scatter src by dst ----------------
__global__ void k_scatter(const int* __restrict__ edge_src,
                          const int* __restrict__ edge_dst) {
    int i = blockIdx.x * blockDim.x + threadIdx.x;
    if (i >= PE) return;
    int p = i / NE;
    int dst = edge_dst[i];
    int src = edge_src[i];
    int seg = p * NNODE + dst;
    int pos = atomicAdd(&g_cursor[seg], 1);
    g_esrc[g_off[seg] + pos] = src;
}

// ---------------- K4: GAT aggregate (warp per (p,node)) ----------------
__global__ void __launch_bounds__(256) k_agg(const float* __restrict__ bias) {
    int gw = (blockIdx.x * blockDim.x + threadIdx.x) >> 5;
    if (gw >= PN) return;
    int lane = threadIdx.x & 31;
    int p = gw / NNODE;
    int start = g_off[gw];
    int cnt = g_count[gw];
    const float4 er4 = *(const float4*)&g_er[gw * NH];
    const float* elbase = &g_el[p * NNODE * NH];
    const float* fbase = &g_feat[(size_t)p * NNODE * HD];

    float m0 = -1e30f, m1 = -1e30f, m2 = -1e30f, m3 = -1e30f;
    for (int i = 0; i < cnt; i++) {
        int src = g_esrc[start + i];
        float4 el4 = *(const float4*)&elbase[src * NH];
        float e0 = el4.x + er4.x; e0 = e0 > 0.f ? e0 : NEG_SLOPE * e0;
        float e1 = el4.y + er4.y; e1 = e1 > 0.f ? e1 : NEG_SLOPE * e1;
        float e2 = el4.z + er4.z; e2 = e2 > 0.f ? e2 : NEG_SLOPE * e2;
        float e3 = el4.w + er4.w; e3 = e3 > 0.f ? e3 : NEG_SLOPE * e3;
        m0 = fmaxf(m0, e0); m1 = fmaxf(m1, e1);
        m2 = fmaxf(m2, e2); m3 = fmaxf(m3, e3);
    }
    float s0 = 0.f, s1 = 0.f, s2 = 0.f, s3 = 0.f;
    for (int i = 0; i < cnt; i++) {
        int src = g_esrc[start + i];
        float4 el4 = *(const float4*)&elbase[src * NH];
        float e0 = el4.x + er4.x; e0 = e0 > 0.f ? e0 : NEG_SLOPE * e0;
        float e1 = el4.y + er4.y; e1 = e1 > 0.f ? e1 : NEG_SLOPE * e1;
        float e2 = el4.z + er4.z; e2 = e2 > 0.f ? e2 : NEG_SLOPE * e2;
        float e3 = el4.w + er4.w; e3 = e3 > 0.f ? e3 : NEG_SLOPE * e3;
        s0 += __expf(e0 - m0); s1 += __expf(e1 - m1);
        s2 += __expf(e2 - m2); s3 += __expf(e3 - m3);
    }
    float r0 = 1.f / fmaxf(s0, 1e-9f);
    float r1 = 1.f / fmaxf(s1, 1e-9f);
    float r2 = 1.f / fmaxf(s2, 1e-9f);
    float r3 = 1.f / fmaxf(s3, 1e-9f);

    const float* bp = bias + p * HD;
    float a0 = bp[lane], a1 = bp[lane + 32], a2 = bp[lane + 64], a3 = bp[lane + 96];
    for (int i = 0; i < cnt; i++) {
        int src = g_esrc[start + i];
        float4 el4 = *(const float4*)&elbase[src * NH];
        float e0 = el4.x + er4.x; e0 = e0 > 0.f ? e0 : NEG_SLOPE * e0;
        float e1 = el4.y + er4.y; e1 = e1 > 0.f ? e1 : NEG_SLOPE * e1;
        float e2 = el4.z + er4.z; e2 = e2 > 0.f ? e2 : NEG_SLOPE * e2;
        float e3 = el4.w + er4.w; e3 = e3 > 0.f ? e3 : NEG_SLOPE * e3;
        float w0 = __expf(e0 - m0) * r0;
        float w1 = __expf(e1 - m1) * r1;
        float w2 = __expf(e2 - m2) * r2;
        float w3 = __expf(e3 - m3) * r3;
        const float* f = &fbase[(size_t)src * HD + lane];
        a0 += w0 * f[0];
        a1 += w1 * f[32];
        a2 += w2 * f[64];
        a3 += w3 * f[96];
    }
    float* zp = &g_z[(size_t)gw * HD + lane];
    zp[0] = a0; zp[32] = a1; zp[64] = a2; zp[96] = a3;
}

// ---------------- K5: semantic attention score (warp per (p,n)) ----------------
__global__ void __launch_bounds__(256) k_sem(const float* __restrict__ sa_w1,
                                             const float* __restrict__ sa_b1,
                                             const float* __restrict__ sa_w2) {
    __shared__ float w1s[HD * HID];  // 32 KB
    for (int i = threadIdx.x; i < HD * HID / 4; i += 256)
        ((float4*)w1s)[i] = ((const float4*)sa_w1)[i];
    __syncthreads();

    int gw = (blockIdx.x * blockDim.x + threadIdx.x) >> 5;
    if (gw >= PN) return;
    int lane = threadIdx.x & 31;
    float h0 = sa_b1[lane], h1 = sa_b1[lane + 32];
    const float* zr = &g_z[(size_t)gw * HD];
#pragma unroll 4
    for (int k = 0; k < HD; k++) {
        float zk = zr[k];
        h0 += zk * w1s[k * HID + lane];
        h1 += zk * w1s[k * HID + lane + 32];
    }
    float sc = tanhf(h0) * sa_w2[lane] + tanhf(h1) * sa_w2[lane + 32];
#pragma unroll
    for (int o = 16; o > 0; o >>= 1) sc += __shfl_xor_sync(0xffffffffu, sc, o);
    if (lane == 0) {
        int p = gw / NNODE;
        atomicAdd(&g_wsum[p], sc);
    }
}

// ---------------- K6: final weighted sum ----------------
__global__ void k_final(float* __restrict__ out) {
    int idx = blockIdx.x * blockDim.x + threadIdx.x;
    if (idx >= NNODE * HD) return;
    float w0 = g_wsum[0] * (1.f / NNODE);
    float w1 = g_wsum[1] * (1.f / NNODE);
    float w2 = g_wsum[2] * (1.f / NNODE);
    float mx = fmaxf(w0, fmaxf(w1, w2));
    float b0 = __expf(w0 - mx), b1 = __expf(w1 - mx), b2 = __expf(w2 - mx);
    float inv = 1.f / (b0 + b1 + b2);
    int n = idx >> 7, c = idx & 127;
    size_t base = (size_t)n * HD + c;
    out[idx] = (b0 * g_z[base] +
                b1 * g_z[(size_t)NNODE * HD + base] +
                b2 * g_z[(size_t)2 * NNODE * HD + base]) * inv;
}

// ---------------- launch ----------------
extern "C" void kernel_launch(void* const* d_in, const int* in_sizes, int n_in,
                              void* d_out, int out_size) {
    const float* h    = (const float*)d_in[0];
    const int*   esrc = (const int*)d_in[1];
    const int*   edst = (const int*)d_in[2];
    const float* W    = (const float*)d_in[3];
    const float* al   = (const float*)d_in[4];
    const float* ar   = (const float*)d_in[5];
    const float* bias = (const float*)d_in[6];
    const float* w1   = (const float*)d_in[7];
    const float* b1   = (const float*)d_in[8];
    const float* w2   = (const float*)d_in[9];
    float* out = (float*)d_out;

    k_init<<<(PN + 255) / 256, 256>>>();
    k_gemm<<<dim3((NNODE + 63) / 64, NP), 256>>>(h, W, al, ar);
    k_count<<<(PE + 255) / 256, 256>>>(edst);
    k_scan_blocks<<<NB, 256>>>();
    k_scan_bsums<<<1, 512>>>();
    k_scan_final<<<NB, 256>>>();
    k_scatter<<<(PE + 255) / 256, 256>>>(esrc, edst);
    k_agg<<<PN / 8, 256>>>(bias);
    k_sem<<<PN / 8, 256>>>(w1, b1, w2);
    k_final<<<(NNODE * HD + 255) / 256, 256>>>(out);
}

// round 4
// speedup vs baseline: 1.7000x; 1.7000x over previous
#include <cuda_runtime.h>
#include <cuda_bf16.h>
#include <math.h>
#include <stdint.h>

#define NNODE 100000
#define NP 3
#define NE 800000
#define INF 128
#define NH 4
#define HD 128
#define HID 64
#define PN (NP*NNODE)
#define PE (NP*NE)
#define NEG_SLOPE 0.2f

#define SCAN_ITEMS 1024
#define NB ((PN + SCAN_ITEMS - 1) / SCAN_ITEMS)   // 293
#define MBLK ((NNODE + 127) / 128)                // 782

// ---------------- device scratch (static, no allocations) ----------------
__device__ __align__(16) float g_feat[(size_t)NP * NNODE * HD];
__device__ __align__(16) float g_z[(size_t)NP * NNODE * HD];
__device__ __align__(16) float g_el[PN * NH];
__device__ __align__(16) float g_er[PN * NH];
__device__ __align__(16) float g_ex[(size_t)PE * NH];   // exp weights, CSR order
__device__ int   g_count[PN];
__device__ int   g_cursor[PN];
__device__ int   g_off[PN];
__device__ int   g_bsums[512];
__device__ int   g_esrc[PE];   // src ids grouped by (p,dst)
__device__ int   g_epos[PE];   // CSR slot of original edge i
__device__ float g_wsum[NP];

// ---------------- helpers ----------------
__device__ __forceinline__ float totf32(float x) {
    uint32_t u; asm("cvt.rna.tf32.f32 %0, %1;" : "=r"(u) : "f"(x));
    return __uint_as_float(u);
}
__device__ __forceinline__ void mma8(float* d, uint32_t a0, uint32_t a1,
                                     uint32_t a2, uint32_t a3,
                                     uint32_t b0, uint32_t b1) {
    asm("mma.sync.aligned.m16n8k8.row.col.f32.tf32.tf32.f32 "
        "{%0,%1,%2,%3},{%4,%5,%6,%7},{%8,%9},{%0,%1,%2,%3};"
        : "+f"(d[0]), "+f"(d[1]), "+f"(d[2]), "+f"(d[3])
        : "r"(a0), "r"(a1), "r"(a2), "r"(a3), "r"(b0), "r"(b1));
}
__device__ __forceinline__ float tanhfast(float x) {
    float y; asm("tanh.approx.f32 %0, %1;" : "=f"(y) : "f"(x)); return y;
}
__device__ __forceinline__ float pick4(float4 v, int h) {
    float r = v.x;
    r = (h == 1) ? v.y : r;
    r = (h == 2) ? v.z : r;
    r = (h == 3) ? v.w : r;
    return r;
}

// ---------------- K0: init ----------------
__global__ void k_init() {
    int i = blockIdx.x * blockDim.x + threadIdx.x;
    if (i < PN) { g_count[i] = 0; g_cursor[i] = 0; }
    if (i < NP) g_wsum[i] = 0.f;
}

// ---------------- K1: feat = h @ W_p via tf32 mma, fused el/er ----------------
// block 256 (8 warps); tile M=128, N=128, K chunks of 32; warp w -> rows w*16.
__global__ void __launch_bounds__(256) k_gemm(const float* __restrict__ h,
                                              const float* __restrict__ W,
                                              const float* __restrict__ attn_l,
                                              const float* __restrict__ attn_r) {
    __shared__ float As[128 * 36];   // A tile (tf32 bits), pitch 36
    __shared__ float Ws[32 * 136];   // B chunk (tf32 bits), pitch 136 (==8 mod 32)

    const int p = blockIdx.y;
    const int row0 = blockIdx.x * 128;
    const int tid = threadIdx.x;
    const int w = tid >> 5, lane = tid & 31;
    const int gid = lane >> 2, tig = lane & 3;
    const float* Wp = W + (size_t)p * INF * HD;

    float acc[16][4];
#pragma unroll
    for (int t = 0; t < 16; t++) { acc[t][0] = acc[t][1] = acc[t][2] = acc[t][3] = 0.f; }

    for (int kc = 0; kc < 4; kc++) {
        // stage A: rows row0..row0+127, cols kc*32..+31 (1024 float4)
        for (int i = tid; i < 1024; i += 256) {
            int r = i >> 3, q = i & 7;
            float4 v = make_float4(0.f, 0.f, 0.f, 0.f);
            if (row0 + r < NNODE)
                v = *(const float4*)(h + (size_t)(row0 + r) * INF + kc * 32 + q * 4);
            float4 o = make_float4(totf32(v.x), totf32(v.y), totf32(v.z), totf32(v.w));
            *(float4*)&As[r * 36 + q * 4] = o;
        }
        // stage B: W rows kc*32..+31, all 128 cols (1024 float4)
        for (int i = tid; i < 1024; i += 256) {
            int r = i >> 5, q = i & 31;
            float4 v = *(const float4*)(Wp + (size_t)(kc * 32 + r) * HD + q * 4);
            float4 o = make_float4(totf32(v.x), totf32(v.y), totf32(v.z), totf32(v.w));
            *(float4*)&Ws[r * 136 + q * 4] = o;
        }
        __syncthreads();

#pragma unroll
        for (int ks = 0; ks < 4; ks++) {
            int kb = ks * 8;
            uint32_t a0 = __float_as_uint(As[(w * 16 + gid) * 36 + kb + tig]);
            uint32_t a1 = __float_as_uint(As[(w * 16 + gid + 8) * 36 + kb + tig]);
            uint32_t a2 = __float_as_uint(As[(w * 16 + gid) * 36 + kb + tig + 4]);
            uint32_t a3 = __float_as_uint(As[(w * 16 + gid + 8) * 36 + kb + tig + 4]);
#pragma unroll
            for (int nt = 0; nt < 16; nt++) {
                uint32_t b0 = __float_as_uint(Ws[(kb + tig) * 136 + nt * 8 + gid]);
                uint32_t b1 = __float_as_uint(Ws[(kb + tig + 4) * 136 + nt * 8 + gid]);
                mma8(acc[nt], a0, a1, a2, a3, b0, b1);
            }
        }
        __syncthreads();
    }

    // epilogue: store feat + reduce el/er
    const int r0 = row0 + w * 16 + gid;
    const int r1 = r0 + 8;
    const bool ok0 = r0 < NNODE, ok1 = r1 < NNODE;

#pragma unroll
    for (int nt = 0; nt < 16; nt++) {
        int c = nt * 8 + tig * 2;
        if (ok0) *(float2*)&g_feat[((size_t)p * NNODE + r0) * HD + c] =
            make_float2(acc[nt][0], acc[nt][1]);
        if (ok1) *(float2*)&g_feat[((size_t)p * NNODE + r1) * HD + c] =
            make_float2(acc[nt][2], acc[nt][3]);
    }

    const float* alp = attn_l + p * HD;
    const float* arp = attn_r + p * HD;
#pragma unroll
    for (int hd = 0; hd < 4; hd++) {
        float vl0 = 0.f, vl1 = 0.f, vr0 = 0.f, vr1 = 0.f;
#pragma unroll
        for (int t = 0; t < 4; t++) {
            int nt = hd * 4 + t;
            int c = nt * 8 + tig * 2;
            float w0 = alp[c], w1 = alp[c + 1];
            float u0 = arp[c], u1 = arp[c + 1];
            vl0 += acc[nt][0] * w0 + acc[nt][1] * w1;
            vl1 += acc[nt][2] * w0 + acc[nt][3] * w1;
            vr0 += acc[nt][0] * u0 + acc[nt][1] * u1;
            vr1 += acc[nt][2] * u0 + acc[nt][3] * u1;
        }
        vl0 += __shfl_xor_sync(0xffffffffu, vl0, 1); vl0 += __shfl_xor_sync(0xffffffffu, vl0, 2);
        vl1 += __shfl_xor_sync(0xffffffffu, vl1, 1); vl1 += __shfl_xor_sync(0xffffffffu, vl1, 2);
        vr0 += __shfl_xor_sync(0xffffffffu, vr0, 1); vr0 += __shfl_xor_sync(0xffffffffu, vr0, 2);
        vr1 += __shfl_xor_sync(0xffffffffu, vr1, 1); vr1 += __shfl_xor_sync(0xffffffffu, vr1, 2);
        if (tig == 0) {
            if (ok0) { g_el[(p * NNODE + r0) * NH + hd] = vl0;
                       g_er[(p * NNODE + r0) * NH + hd] = vr0; }
            if (ok1) { g_el[(p * NNODE + r1) * NH + hd] = vl1;
                       g_er[(p * NNODE + r1) * NH + hd] = vr1; }
        }
    }
}

// ---------------- K2: count in-degree ----------------
__global__ void k_count(const int* __restrict__ edge_dst) {
    int i = blockIdx.x * blockDim.x + threadIdx.x;
    if (i >= PE) return;
    int p = i / NE;
    atomicAdd(&g_count[p * NNODE + edge_dst[i]], 1);
}

// ---------------- scan (3 kernels) ----------------
__global__ void k_scan_blocks() {
    __shared__ int s[256];
    int base = blockIdx.x * SCAN_ITEMS;
    int t = threadIdx.x;
    int v = 0;
#pragma unroll
    for (int i = 0; i < 4; i++) {
        int idx = base + t * 4 + i;
        if (idx < PN) v += g_count[idx];
    }
    s[t] = v; __syncthreads();
    for (int o = 128; o > 0; o >>= 1) {
        if (t < o) s[t] += s[t + o];
        __syncthreads();
    }
    if (t == 0) g_bsums[blockIdx.x] = s[0];
}

__global__ void k_scan_bsums() {
    __shared__ int s[512];
    int t = threadIdx.x;
    int v = (t < NB) ? g_bsums[t] : 0;
    s[t] = v; __syncthreads();
    for (int o = 1; o < 512; o <<= 1) {
        int x = (t >= o) ? s[t - o] : 0;
        __syncthreads();
        s[t] += x;
        __syncthreads();
    }
    if (t < NB) g_bsums[t] = s[t] - v;  // exclusive
}

__global__ void k_scan_final() {
    __shared__ int s[256];
    int base = blockIdx.x * SCAN_ITEMS;
    int t = threadIdx.x;
    int loc[4]; int sum = 0;
#pragma unroll
    for (int i = 0; i < 4; i++) {
        int idx = base + t * 4 + i;
        loc[i] = (idx < PN) ? g_count[idx] : 0;
        sum += loc[i];
    }
    s[t] = sum; __syncthreads();
    for (int o = 1; o < 256; o <<= 1) {
        int x = (t >= o) ? s[t - o] : 0;
        __syncthreads();
        s[t] += x;
        __syncthreads();
    }
    int ex = s[t] - sum + g_bsums[blockIdx.x];
#pragma unroll
    for (int i = 0; i < 4; i++) {
        int idx = base + t * 4 + i;
        if (idx < PN) { g_off[idx] = ex; ex += loc[i]; }
    }
}

// ---------------- K3: scatter src by dst, record slot ----------------
__global__ void k_scatter(const int* __restrict__ edge_src,
                          const int* __restrict__ edge_dst) {
    int i = blockIdx.x * blockDim.x + threadIdx.x;
    if (i >= PE) return;
    int p = i / NE;
    int seg = p * NNODE + edge_dst[i];
    int pos = atomicAdd(&g_cursor[seg], 1);
    int at = g_off[seg] + pos;
    g_esrc[at] = edge_src[i];
    g_epos[i] = at;
}

// ---------------- K4a: edge-parallel exp (one thread per edge) ----------------
__global__ void k_p1(const int* __restrict__ edge_src,
                     const int* __restrict__ edge_dst) {
    int i = blockIdx.x * blockDim.x + threadIdx.x;
    if (i >= PE) return;
    int p = i / NE;
    int src = edge_src[i], dst = edge_dst[i];
    float4 el4 = *(const float4*)&g_el[(p * NNODE + src) * NH];
    float4 er4 = *(const float4*)&g_er[(p * NNODE + dst) * NH];
    float e0 = el4.x + er4.x; e0 = e0 > 0.f ? e0 : NEG_SLOPE * e0;
    float e1 = el4.y + er4.y; e1 = e1 > 0.f ? e1 : NEG_SLOPE * e1;
    float e2 = el4.z + er4.z; e2 = e2 > 0.f ? e2 : NEG_SLOPE * e2;
    float e3 = el4.w + er4.w; e3 = e3 > 0.f ? e3 : NEG_SLOPE * e3;
    float4 ex = make_float4(__expf(e0), __expf(e1), __expf(e2), __expf(e3));
    *(float4*)&g_ex[(size_t)g_epos[i] * NH] = ex;
}

// ---------------- K4b: gather (warp per (p,node); lane owns 4 cols) ----------------
__global__ void __launch_bounds__(256) k_p2(const float* __restrict__ bias) {
    int gw = (blockIdx.x * blockDim.x + threadIdx.x) >> 5;
    if (gw >= PN) return;
    int lane = threadIdx.x & 31;
    int p = gw / NNODE;
    int start = g_off[gw];
    int cnt = g_count[gw];
    int hd = lane >> 3;   // head owning cols 4*lane..4*lane+3

    float4 s = make_float4(0.f, 0.f, 0.f, 0.f);
    for (int i = 0; i < cnt; i++) {
        float4 ex = *(const float4*)&g_ex[(size_t)(start + i) * NH];
        s.x += ex.x; s.y += ex.y; s.z += ex.z; s.w += ex.w;
    }
    float r = 1.f / fmaxf(pick4(s, hd), 1e-9f);

    float4 a = *(const float4*)&bias[p * HD + lane * 4];
    const float* fb = g_feat + (size_t)p * NNODE * HD;
    for (int i = 0; i < cnt; i++) {
        int src = g_esrc[start + i];
        float4 ex = *(const float4*)&g_ex[(size_t)(start + i) * NH];
        float wgt = pick4(ex, hd) * r;
        float4 f = *(const float4*)&fb[(size_t)src * HD + lane * 4];
        a.x += wgt * f.x; a.y += wgt * f.y; a.z += wgt * f.z; a.w += wgt * f.w;
    }
    *(float4*)&g_z[(size_t)gw * HD + lane * 4] = a;
}

// ---------------- K5: semantic score via tf32 mma + fast tanh + full reduce ----------------
__global__ void __launch_bounds__(256) k_sem(const float* __restrict__ sa_w1,
                                             const float* __restrict__ sa_b1,
                                             const float* __restrict__ sa_w2) {
    __shared__ float Zs[128 * 36];  // z tile (tf32 bits)
    __shared__ float W1s[32 * 72];  // w1 chunk (tf32 bits), pitch 72 (==8 mod 32)
    __shared__ float s_sum;

    const int p = blockIdx.y;
    const int row0 = blockIdx.x * 128;
    const int tid = threadIdx.x;
    const int w = tid >> 5, lane = tid & 31;
    const int gid = lane >> 2, tig = lane & 3;
    if (tid == 0) s_sum = 0.f;

    float acc[8][4];
#pragma unroll
    for (int t = 0; t < 8; t++) { acc[t][0] = acc[t][1] = acc[t][2] = acc[t][3] = 0.f; }

    const float* zb = g_z + (size_t)p * NNODE * HD;
    for (int kc = 0; kc < 4; kc++) {
        for (int i = tid; i < 1024; i += 256) {
            int r = i >> 3, q = i & 7;
            float4 v = make_float4(0.f, 0.f, 0.f, 0.f);
            if (row0 + r < NNODE)
                v = *(const float4*)(zb + (size_t)(row0 + r) * HD + kc * 32 + q * 4);
            float4 o = make_float4(totf32(v.x), totf32(v.y), totf32(v.z), totf32(v.w));
            *(float4*)&Zs[r * 36 + q * 4] = o;
        }
        for (int i = tid; i < 512; i += 256) {
            int r = i >> 4, q = i & 15;
            float4 v = *(const float4*)(sa_w1 + (size_t)(kc * 32 + r) * HID + q * 4);
            float4 o = make_float4(totf32(v.x), totf32(v.y), totf32(v.z), totf32(v.w));
            *(float4*)&W1s[r * 72 + q * 4] = o;
        }
        __syncthreads();

#pragma unroll
        for (int ks = 0; ks < 4; ks++) {
            int kb = ks * 8;
            uint32_t a0 = __float_as_uint(Zs[(w * 16 + gid) * 36 + kb + tig]);
            uint32_t a1 = __float_as_uint(Zs[(w * 16 + gid + 8) * 36 + kb + tig]);
            uint32_t a2 = __float_as_uint(Zs[(w * 16 + gid) * 36 + kb + tig + 4]);
            uint32_t a3 = __float_as_uint(Zs[(w * 16 + gid + 8) * 36 + kb + tig + 4]);
#pragma unroll
            for (int nt = 0; nt < 8; nt++) {
                uint32_t b0 = __float_as_uint(W1s[(kb + tig) * 72 + nt * 8 + gid]);
                uint32_t b1 = __float_as_uint(W1s[(kb + tig + 4) * 72 + nt * 8 + gid]);
                mma8(acc[nt], a0, a1, a2, a3, b0, b1);
            }
        }
        __syncthreads();
    }

    const int r0 = row0 + w * 16 + gid;
    const int r1 = r0 + 8;
    const float m0 = (r0 < NNODE) ? 1.f : 0.f;
    const float m1 = (r1 < NNODE) ? 1.f : 0.f;

    float part = 0.f;
#pragma unroll
    for (int nt = 0; nt < 8; nt++) {
        int c = nt * 8 + tig * 2;
        float bb0 = sa_b1[c], bb1 = sa_b1[c + 1];
        float w20 = sa_w2[c], w21 = sa_w2[c + 1];
        part += m0 * (tanhfast(acc[nt][0] + bb0) * w20 + tanhfast(acc[nt][1] + bb1) * w21);
        part += m1 * (tanhfast(acc[nt][2] + bb0) * w20 + tanhfast(acc[nt][3] + bb1) * w21);
    }
#pragma unroll
    for (int o = 16; o > 0; o >>= 1) part += __shfl_xor_sync(0xffffffffu, part, o);
    if (lane == 0) atomicAdd(&s_sum, part);
    __syncthreads();
    if (tid == 0) atomicAdd(&g_wsum[p], s_sum);
}

// ---------------- K6: final weighted sum ----------------
__global__ void k_final(float* __restrict__ out) {
    int idx = blockIdx.x * blockDim.x + threadIdx.x;
    if (idx >= NNODE * HD) return;
    float w0 = g_wsum[0] * (1.f / NNODE);
    float w1 = g_wsum[1] * (1.f / NNODE);
    float w2 = g_wsum[2] * (1.f / NNODE);
    float mx = fmaxf(w0, fmaxf(w1, w2));
    float b0 = __expf(w0 - mx), b1 = __expf(w1 - mx), b2 = __expf(w2 - mx);
    float inv = 1.f / (b0 + b1 + b2);
    out[idx] = (b0 * g_z[idx] +
                b1 * g_z[(size_t)NNODE * HD + idx] +
                b2 * g_z[(size_t)2 * NNODE * HD + idx]) * inv;
}

// ---------------- launch ----------------
extern "C" void kernel_launch(void* const* d_in, const int* in_sizes, int n_in,
                              void* d_out, int out_size) {
    const float* h    = (const float*)d_in[0];
    const int*   esrc = (const int*)d_in[1];
    const int*   edst = (const int*)d_in[2];
    const float* W    = (const float*)d_in[3];
    const float* al   = (const float*)d_in[4];
    const float* ar   = (const float*)d_in[5];
    const float* bias = (const float*)d_in[6];
    const float* w1   = (const float*)d_in[7];
    const float* b1   = (const float*)d_in[8];
    const float* w2   = (const float*)d_in[9];
    float* out = (float*)d_out;

    k_init<<<(PN + 255) / 256, 256>>>();
    k_gemm<<<dim3(MBLK, NP), 256>>>(h, W, al, ar);
    k_count<<<(PE + 255) / 256, 256>>>(edst);
    k_scan_blocks<<<NB, 256>>>();
    k_scan_bsums<<<1, 512>>>();
    k_scan_final<<<NB, 256>>>();
    k_scatter<<<(PE + 255) / 256, 256>>>(esrc, edst);
    k_p1<<<(PE + 255) / 256, 256>>>(esrc, edst);
    k_p2<<<PN / 8, 256>>>(bias);
    k_sem<<<dim3(MBLK, NP), 256>>>(w1, b1, w2);
    k_final<<<(NNODE * HD + 255) / 256, 256>>>(out);
}

// round 5
// speedup vs baseline: 2.3208x; 1.3652x over previous
#include <cuda_runtime.h>
#include <cuda_bf16.h>
#include <math.h>
#include <stdint.h>

#define NNODE 100000
#define NP 3
#define NE 800000
#define INF 128
#define NH 4
#define HD 128
#define HID 64
#define PN (NP*NNODE)
#define PE (NP*NE)
#define NEG_SLOPE 0.2f

#define SCAN_ITEMS 1024
#define NB ((PN + SCAN_ITEMS - 1) / SCAN_ITEMS)   // 293
#define MBLK ((NNODE + 127) / 128)                // 782

// ---------------- device scratch (static, no allocations) ----------------
__device__ __align__(16) float g_feat[(size_t)NP * NNODE * HD];
__device__ __align__(16) float g_z[(size_t)NP * NNODE * HD];
__device__ __align__(16) float g_el[PN * NH];
__device__ __align__(16) float g_er[PN * NH];
__device__ int   g_count[PN];
__device__ int   g_cursor[PN];
__device__ int   g_off[PN];
__device__ int   g_bsums[512];
__device__ int   g_esrc[PE];   // src ids grouped by (p,dst)
__device__ float g_wsum[NP];

// ---------------- helpers ----------------
__device__ __forceinline__ float totf32(float x) {
    uint32_t u; asm("cvt.rna.tf32.f32 %0, %1;" : "=r"(u) : "f"(x));
    return __uint_as_float(u);
}
__device__ __forceinline__ void mma8(float* d, uint32_t a0, uint32_t a1,
                                     uint32_t a2, uint32_t a3,
                                     uint32_t b0, uint32_t b1) {
    asm("mma.sync.aligned.m16n8k8.row.col.f32.tf32.tf32.f32 "
        "{%0,%1,%2,%3},{%4,%5,%6,%7},{%8,%9},{%0,%1,%2,%3};"
        : "+f"(d[0]), "+f"(d[1]), "+f"(d[2]), "+f"(d[3])
        : "r"(a0), "r"(a1), "r"(a2), "r"(a3), "r"(b0), "r"(b1));
}
__device__ __forceinline__ float tanhfast(float x) {
    float y; asm("tanh.approx.f32 %0, %1;" : "=f"(y) : "f"(x)); return y;
}
__device__ __forceinline__ float pick4(float4 v, int h) {
    float r = v.x;
    r = (h == 1) ? v.y : r;
    r = (h == 2) ? v.z : r;
    r = (h == 3) ? v.w : r;
    return r;
}
__device__ __forceinline__ float lrelu(float e) {
    return fmaxf(e, NEG_SLOPE * e);
}
__device__ __forceinline__ float4 edge_exp(const float* __restrict__ elbase,
                                           int src, float4 er4) {
    float4 el4 = *(const float4*)&elbase[src * NH];
    return make_float4(__expf(lrelu(el4.x + er4.x)),
                       __expf(lrelu(el4.y + er4.y)),
                       __expf(lrelu(el4.z + er4.z)),
                       __expf(lrelu(el4.w + er4.w)));
}

// ---------------- K0: init ----------------
__global__ void k_init() {
    int i = blockIdx.x * blockDim.x + threadIdx.x;
    if (i < PN) { g_count[i] = 0; g_cursor[i] = 0; }
    if (i < NP) g_wsum[i] = 0.f;
}

// ---------------- K1: feat = h @ W_p via tf32 mma, fused el/er ----------------
__global__ void __launch_bounds__(256) k_gemm(const float* __restrict__ h,
                                              const float* __restrict__ W,
                                              const float* __restrict__ attn_l,
                                              const float* __restrict__ attn_r) {
    __shared__ float As[128 * 36];
    __shared__ float Ws[32 * 136];

    const int p = blockIdx.y;
    const int row0 = blockIdx.x * 128;
    const int tid = threadIdx.x;
    const int w = tid >> 5, lane = tid & 31;
    const int gid = lane >> 2, tig = lane & 3;
    const float* Wp = W + (size_t)p * INF * HD;

    float acc[16][4];
#pragma unroll
    for (int t = 0; t < 16; t++) { acc[t][0] = acc[t][1] = acc[t][2] = acc[t][3] = 0.f; }

    for (int kc = 0; kc < 4; kc++) {
        for (int i = tid; i < 1024; i += 256) {
            int r = i >> 3, q = i & 7;
            float4 v = make_float4(0.f, 0.f, 0.f, 0.f);
            if (row0 + r < NNODE)
                v = *(const float4*)(h + (size_t)(row0 + r) * INF + kc * 32 + q * 4);
            float4 o = make_float4(totf32(v.x), totf32(v.y), totf32(v.z), totf32(v.w));
            *(float4*)&As[r * 36 + q * 4] = o;
        }
        for (int i = tid; i < 1024; i += 256) {
            int r = i >> 5, q = i & 31;
            float4 v = *(const float4*)(Wp + (size_t)(kc * 32 + r) * HD + q * 4);
            float4 o = make_float4(totf32(v.x), totf32(v.y), totf32(v.z), totf32(v.w));
            *(float4*)&Ws[r * 136 + q * 4] = o;
        }
        __syncthreads();

#pragma unroll
        for (int ks = 0; ks < 4; ks++) {
            int kb = ks * 8;
            uint32_t a0 = __float_as_uint(As[(w * 16 + gid) * 36 + kb + tig]);
            uint32_t a1 = __float_as_uint(As[(w * 16 + gid + 8) * 36 + kb + tig]);
            uint32_t a2 = __float_as_uint(As[(w * 16 + gid) * 36 + kb + tig + 4]);
            uint32_t a3 = __float_as_uint(As[(w * 16 + gid + 8) * 36 + kb + tig + 4]);
#pragma unroll
            for (int nt = 0; nt < 16; nt++) {
                uint32_t b0 = __float_as_uint(Ws[(kb + tig) * 136 + nt * 8 + gid]);
                uint32_t b1 = __float_as_uint(Ws[(kb + tig + 4) * 136 + nt * 8 + gid]);
                mma8(acc[nt], a0, a1, a2, a3, b0, b1);
            }
        }
        __syncthreads();
    }

    const int r0 = row0 + w * 16 + gid;
    const int r1 = r0 + 8;
    const bool ok0 = r0 < NNODE, ok1 = r1 < NNODE;

#pragma unroll
    for (int nt = 0; nt < 16; nt++) {
        int c = nt * 8 + tig * 2;
        if (ok0) *(float2*)&g_feat[((size_t)p * NNODE + r0) * HD + c] =
            make_float2(acc[nt][0], acc[nt][1]);
        if (ok1) *(float2*)&g_feat[((size_t)p * NNODE + r1) * HD + c] =
            make_float2(acc[nt][2], acc[nt][3]);
    }

    const float* alp = attn_l + p * HD;
    const float* arp = attn_r + p * HD;
#pragma unroll
    for (int hd = 0; hd < 4; hd++) {
        float vl0 = 0.f, vl1 = 0.f, vr0 = 0.f, vr1 = 0.f;
#pragma unroll
        for (int t = 0; t < 4; t++) {
            int nt = hd * 4 + t;
            int c = nt * 8 + tig * 2;
            float w0 = alp[c], w1 = alp[c + 1];
            float u0 = arp[c], u1 = arp[c + 1];
            vl0 += acc[nt][0] * w0 + acc[nt][1] * w1;
            vl1 += acc[nt][2] * w0 + acc[nt][3] * w1;
            vr0 += acc[nt][0] * u0 + acc[nt][1] * u1;
            vr1 += acc[nt][2] * u0 + acc[nt][3] * u1;
        }
        vl0 += __shfl_xor_sync(0xffffffffu, vl0, 1); vl0 += __shfl_xor_sync(0xffffffffu, vl0, 2);
        vl1 += __shfl_xor_sync(0xffffffffu, vl1, 1); vl1 += __shfl_xor_sync(0xffffffffu, vl1, 2);
        vr0 += __shfl_xor_sync(0xffffffffu, vr0, 1); vr0 += __shfl_xor_sync(0xffffffffu, vr0, 2);
        vr1 += __shfl_xor_sync(0xffffffffu, vr1, 1); vr1 += __shfl_xor_sync(0xffffffffu, vr1, 2);
        if (tig == 0) {
            if (ok0) { g_el[(p * NNODE + r0) * NH + hd] = vl0;
                       g_er[(p * NNODE + r0) * NH + hd] = vr0; }
            if (ok1) { g_el[(p * NNODE + r1) * NH + hd] = vl1;
                       g_er[(p * NNODE + r1) * NH + hd] = vr1; }
        }
    }
}

// ---------------- K2: count in-degree ----------------
__global__ void k_count(const int* __restrict__ edge_dst) {
    int i = blockIdx.x * blockDim.x + threadIdx.x;
    if (i >= PE) return;
    int p = i / NE;
    atomicAdd(&g_count[p * NNODE + edge_dst[i]], 1);
}

// ---------------- scan (3 kernels) ----------------
__global__ void k_scan_blocks() {
    __shared__ int s[256];
    int base = blockIdx.x * SCAN_ITEMS;
    int t = threadIdx.x;
    int v = 0;
#pragma unroll
    for (int i = 0; i < 4; i++) {
        int idx = base + t * 4 + i;
        if (idx < PN) v += g_count[idx];
    }
    s[t] = v; __syncthreads();
    for (int o = 128; o > 0; o >>= 1) {
        if (t < o) s[t] += s[t + o];
        __syncthreads();
    }
    if (t == 0) g_bsums[blockIdx.x] = s[0];
}

__global__ void k_scan_bsums() {
    __shared__ int s[512];
    int t = threadIdx.x;
    int v = (t < NB) ? g_bsums[t] : 0;
    s[t] = v; __syncthreads();
    for (int o = 1; o < 512; o <<= 1) {
        int x = (t >= o) ? s[t - o] : 0;
        __syncthreads();
        s[t] += x;
        __syncthreads();
    }
    if (t < NB) g_bsums[t] = s[t] - v;  // exclusive
}

__global__ void k_scan_final() {
    __shared__ int s[256];
    int base = blockIdx.x * SCAN_ITEMS;
    int t = threadIdx.x;
    int loc[4]; int sum = 0;
#pragma unroll
    for (int i = 0; i < 4; i++) {
        int idx = base + t * 4 + i;
        loc[i] = (idx < PN) ? g_count[idx] : 0;
        sum += loc[i];
    }
    s[t] = sum; __syncthreads();
    for (int o = 1; o < 256; o <<= 1) {
        int x = (t >= o) ? s[t - o] : 0;
        __syncthreads();
        s[t] += x;
        __syncthreads();
    }
    int ex = s[t] - sum + g_bsums[blockIdx.x];
#pragma unroll
    for (int i = 0; i < 4; i++) {
        int idx = base + t * 4 + i;
        if (idx < PN) { g_off[idx] = ex; ex += loc[i]; }
    }
}

// ---------------- K3: scatter src by dst ----------------
__global__ void k_scatter(const int* __restrict__ edge_src,
                          const int* __restrict__ edge_dst) {
    int i = blockIdx.x * blockDim.x + threadIdx.x;
    if (i >= PE) return;
    int p = i / NE;
    int seg = p * NNODE + edge_dst[i];
    int pos = atomicAdd(&g_cursor[seg], 1);
    g_esrc[g_off[seg] + pos] = edge_src[i];
}

// ---------------- K4: fused GAT softmax + aggregate (warp per (p,node)) ----------------
__global__ void __launch_bounds__(256) k_p2(const float* __restrict__ bias) {
    int gw = (blockIdx.x * blockDim.x + threadIdx.x) >> 5;
    if (gw >= PN) return;
    const int lane = threadIdx.x & 31;
    const int p = gw / NNODE;
    const int start = g_off[gw];
    const int cnt = g_count[gw];
    const int hd = lane >> 3;   // head owning cols 4*lane..4*lane+3
    const float* elbase = g_el + (size_t)p * NNODE * NH;
    const float* fb = g_feat + (size_t)p * NNODE * HD;
    const float4 er4 = *(const float4*)&g_er[gw * NH];

    float4 a = *(const float4*)&bias[p * HD + lane * 4];

    if (cnt > 0 && cnt <= 32) {
        // fast path: lane L owns edge L; everything register-resident
        int src = 0;
        float4 ex = make_float4(0.f, 0.f, 0.f, 0.f);
        if (lane < cnt) {
            src = g_esrc[start + lane];        // coalesced
            ex = edge_exp(elbase, src, er4);
        }
        float4 s = ex;
#pragma unroll
        for (int o = 16; o > 0; o >>= 1) {
            s.x += __shfl_xor_sync(0xffffffffu, s.x, o);
            s.y += __shfl_xor_sync(0xffffffffu, s.y, o);
            s.z += __shfl_xor_sync(0xffffffffu, s.z, o);
            s.w += __shfl_xor_sync(0xffffffffu, s.w, o);
        }
        float rs = 1.f / fmaxf(pick4(s, hd), 1e-9f);
        for (int j = 0; j < cnt; j++) {
            int sj = __shfl_sync(0xffffffffu, src, j);
            float4 exj = make_float4(__shfl_sync(0xffffffffu, ex.x, j),
                                     __shfl_sync(0xffffffffu, ex.y, j),
                                     __shfl_sync(0xffffffffu, ex.z, j),
                                     __shfl_sync(0xffffffffu, ex.w, j));
            float wgt = pick4(exj, hd) * rs;
            float4 f = *(const float4*)&fb[(size_t)sj * HD + lane * 4];
            a.x += wgt * f.x; a.y += wgt * f.y; a.z += wgt * f.z; a.w += wgt * f.w;
        }
    } else if (cnt > 32) {
        // generic chunked path (rare): sum pass then recompute+gather pass
        float4 s = make_float4(0.f, 0.f, 0.f, 0.f);
        for (int c0 = 0; c0 < cnt; c0 += 32) {
            if (c0 + lane < cnt) {
                int src = g_esrc[start + c0 + lane];
                float4 ex = edge_exp(elbase, src, er4);
                s.x += ex.x; s.y += ex.y; s.z += ex.z; s.w += ex.w;
            }
        }
#pragma unroll
        for (int o = 16; o > 0; o >>= 1) {
            s.x += __shfl_xor_sync(0xffffffffu, s.x, o);
            s.y += __shfl_xor_sync(0xffffffffu, s.y, o);
            s.z += __shfl_xor_sync(0xffffffffu, s.z, o);
            s.w += __shfl_xor_sync(0xffffffffu, s.w, o);
        }
        float rs = 1.f / fmaxf(pick4(s, hd), 1e-9f);
        for (int c0 = 0; c0 < cnt; c0 += 32) {
            int src = 0;
            float4 ex = make_float4(0.f, 0.f, 0.f, 0.f);
            if (c0 + lane < cnt) {
                src = g_esrc[start + c0 + lane];
                ex = edge_exp(elbase, src, er4);
            }
            int lim = min(32, cnt - c0);
            for (int j = 0; j < lim; j++) {
                int sj = __shfl_sync(0xffffffffu, src, j);
                float4 exj = make_float4(__shfl_sync(0xffffffffu, ex.x, j),
                                         __shfl_sync(0xffffffffu, ex.y, j),
                                         __shfl_sync(0xffffffffu, ex.z, j),
                                         __shfl_sync(0xffffffffu, ex.w, j));
                float wgt = pick4(exj, hd) * rs;
                float4 f = *(const float4*)&fb[(size_t)sj * HD + lane * 4];
                a.x += wgt * f.x; a.y += wgt * f.y; a.z += wgt * f.z; a.w += wgt * f.w;
            }
        }
    }
    *(float4*)&g_z[(size_t)gw * HD + lane * 4] = a;
}

// ---------------- K5: semantic score via tf32 mma + fast tanh + full reduce ----------------
__global__ void __launch_bounds__(256) k_sem(const float* __restrict__ sa_w1,
                                             const float* __restrict__ sa_b1,
                                             const float* __restrict__ sa_w2) {
    __shared__ float Zs[128 * 36];
    __shared__ float W1s[32 * 72];
    __shared__ float s_sum;

    const int p = blockIdx.y;
    const int row0 = blockIdx.x * 128;
    const int tid = threadIdx.x;
    const int w = tid >> 5, lane = tid & 31;
    const int gid = lane >> 2, tig = lane & 3;
    if (tid == 0) s_sum = 0.f;

    float acc[8][4];
#pragma unroll
    for (int t = 0; t < 8; t++) { acc[t][0] = acc[t][1] = acc[t][2] = acc[t][3] = 0.f; }

    const float* zb = g_z + (size_t)p * NNODE * HD;
    for (int kc = 0; kc < 4; kc++) {
        for (int i = tid; i < 1024; i += 256) {
            int r = i >> 3, q = i & 7;
            float4 v = make_float4(0.f, 0.f, 0.f, 0.f);
            if (row0 + r < NNODE)
                v = *(const float4*)(zb + (size_t)(row0 + r) * HD + kc * 32 + q * 4);
            float4 o = make_float4(totf32(v.x), totf32(v.y), totf32(v.z), totf32(v.w));
            *(float4*)&Zs[r * 36 + q * 4] = o;
        }
        for (int i = tid; i < 512; i += 256) {
            int r = i >> 4, q = i & 15;
            float4 v = *(const float4*)(sa_w1 + (size_t)(kc * 32 + r) * HID + q * 4);
            float4 o = make_float4(totf32(v.x), totf32(v.y), totf32(v.z), totf32(v.w));
            *(float4*)&W1s[r * 72 + q * 4] = o;
        }
        __syncthreads();

#pragma unroll
        for (int ks = 0; ks < 4; ks++) {
            int kb = ks * 8;
            uint32_t a0 = __float_as_uint(Zs[(w * 16 + gid) * 36 + kb + tig]);
            uint32_t a1 = __float_as_uint(Zs[(w * 16 + gid + 8) * 36 + kb + tig]);
            uint32_t a2 = __float_as_uint(Zs[(w * 16 + gid) * 36 + kb + tig + 4]);
            uint32_t a3 = __float_as_uint(Zs[(w * 16 + gid + 8) * 36 + kb + tig + 4]);
#pragma unroll
            for (int nt = 0; nt < 8; nt++) {
                uint32_t b0 = __float_as_uint(W1s[(kb + tig) * 72 + nt * 8 + gid]);
                uint32_t b1 = __float_as_uint(W1s[(kb + tig + 4) * 72 + nt * 8 + gid]);
                mma8(acc[nt], a0, a1, a2, a3, b0, b1);
            }
        }
        __syncthreads();
    }

    const int r0 = row0 + w * 16 + gid;
    const int r1 = r0 + 8;
    const float m0 = (r0 < NNODE) ? 1.f : 0.f;
    const float m1 = (r1 < NNODE) ? 1.f : 0.f;

    float part = 0.f;
#pragma unroll
    for (int nt = 0; nt < 8; nt++) {
        int c = nt * 8 + tig * 2;
        float bb0 = sa_b1[c], bb1 = sa_b1[c + 1];
        float w20 = sa_w2[c], w21 = sa_w2[c + 1];
        part += m0 * (tanhfast(acc[nt][0] + bb0) * w20 + tanhfast(acc[nt][1] + bb1) * w21);
        part += m1 * (tanhfast(acc[nt][2] + bb0) * w20 + tanhfast(acc[nt][3] + bb1) * w21);
    }
#pragma unroll
    for (int o = 16; o > 0; o >>= 1) part += __shfl_xor_sync(0xffffffffu, part, o);
    if (lane == 0) atomicAdd(&s_sum, part);
    __syncthreads();
    if (tid == 0) atomicAdd(&g_wsum[p], s_sum);
}

// ---------------- K6: final weighted sum ----------------
__global__ void k_final(float* __restrict__ out) {
    int idx = blockIdx.x * blockDim.x + threadIdx.x;
    if (idx >= NNODE * HD) return;
    float w0 = g_wsum[0] * (1.f / NNODE);
    float w1 = g_wsum[1] * (1.f / NNODE);
    float w2 = g_wsum[2] * (1.f / NNODE);
    float mx = fmaxf(w0, fmaxf(w1, w2));
    float b0 = __expf(w0 - mx), b1 = __expf(w1 - mx), b2 = __expf(w2 - mx);
    float inv = 1.f / (b0 + b1 + b2);
    out[idx] = (b0 * g_z[idx] +
                b1 * g_z[(size_t)NNODE * HD + idx] +
                b2 * g_z[(size_t)2 * NNODE * HD + idx]) * inv;
}

// ---------------- launch ----------------
extern "C" void kernel_launch(void* const* d_in, const int* in_sizes, int n_in,
                              void* d_out, int out_size) {
    const float* h    = (const float*)d_in[0];
    const int*   esrc = (const int*)d_in[1];
    const int*   edst = (const int*)d_in[2];
    const float* W    = (const float*)d_in[3];
    const float* al   = (const float*)d_in[4];
    const float* ar   = (const float*)d_in[5];
    const float* bias = (const float*)d_in[6];
    const float* w1   = (const float*)d_in[7];
    const float* b1   = (const float*)d_in[8];
    const float* w2   = (const float*)d_in[9];
    float* out = (float*)d_out;

    // CSR build first; k_gemm placed 6th so the ncu window catches it.
    k_init<<<(PN + 255) / 256, 256>>>();
    k_count<<<(PE + 255) / 256, 256>>>(edst);
    k_scan_blocks<<<NB, 256>>>();
    k_scan_bsums<<<1, 512>>>();
    k_scan_final<<<NB, 256>>>();
    k_gemm<<<dim3(MBLK, NP), 256>>>(h, W, al, ar);
    k_scatter<<<(PE + 255) / 256, 256>>>(esrc, edst);
    k_p2<<<PN / 8, 256>>>(bias);
    k_sem<<<dim3(MBLK, NP), 256>>>(w1, b1, w2);
    k_final<<<(NNODE * HD + 255) / 256, 256>>>(out);
}

// round 6
// speedup vs baseline: 2.6311x; 1.1337x over previous
#include <cuda_runtime.h>
#include <cuda_fp16.h>
#include <math.h>
#include <stdint.h>

#define NNODE 100000
#define NP 3
#define NE 800000
#define INF 128
#define NH 4
#define HD 128
#define HID 64
#define PN (NP*NNODE)
#define PE (NP*NE)
#define NEG_SLOPE 0.2f

#define SCAN_ITEMS 1024
#define NB ((PN + SCAN_ITEMS - 1) / SCAN_ITEMS)   // 293
#define MBLK ((NNODE + 127) / 128)                // 782

// ---------------- device scratch (static, no allocations) ----------------
__device__ __align__(16) __half g_feat[(size_t)NP * NNODE * HD];  // fp16 projected feats
__device__ __align__(16) float g_z[(size_t)NP * NNODE * HD];
__device__ __align__(16) float g_el[PN * NH];
__device__ __align__(16) float g_er[PN * NH];
__device__ int   g_count[PN];
__device__ int   g_cursor[PN];
__device__ int   g_off[PN];
__device__ int   g_bsums[512];
__device__ int   g_esrc[PE];   // src ids grouped by (p,dst)
__device__ float g_wsum[NP];

// ---------------- helpers ----------------
__device__ __forceinline__ float totf32(float x) {
    uint32_t u; asm("cvt.rna.tf32.f32 %0, %1;" : "=r"(u) : "f"(x));
    return __uint_as_float(u);
}
__device__ __forceinline__ void mma8(float* d, uint32_t a0, uint32_t a1,
                                     uint32_t a2, uint32_t a3,
                                     uint32_t b0, uint32_t b1) {
    asm("mma.sync.aligned.m16n8k8.row.col.f32.tf32.tf32.f32 "
        "{%0,%1,%2,%3},{%4,%5,%6,%7},{%8,%9},{%0,%1,%2,%3};"
        : "+f"(d[0]), "+f"(d[1]), "+f"(d[2]), "+f"(d[3])
        : "r"(a0), "r"(a1), "r"(a2), "r"(a3), "r"(b0), "r"(b1));
}
__device__ __forceinline__ float tanhfast(float x) {
    float y; asm("tanh.approx.f32 %0, %1;" : "=f"(y) : "f"(x)); return y;
}
__device__ __forceinline__ float pick4(float4 v, int h) {
    float r = v.x;
    r = (h == 1) ? v.y : r;
    r = (h == 2) ? v.z : r;
    r = (h == 3) ? v.w : r;
    return r;
}
__device__ __forceinline__ float lrelu(float e) {
    return fmaxf(e, NEG_SLOPE * e);
}
__device__ __forceinline__ float4 edge_exp(const float* __restrict__ elbase,
                                           int src, float4 er4) {
    float4 el4 = *(const float4*)&elbase[src * NH];
    return make_float4(__expf(lrelu(el4.x + er4.x)),
                       __expf(lrelu(el4.y + er4.y)),
                       __expf(lrelu(el4.z + er4.z)),
                       __expf(lrelu(el4.w + er4.w)));
}

// ---------------- K0: init ----------------
__global__ void k_init() {
    int i = blockIdx.x * blockDim.x + threadIdx.x;
    if (i < PN) { g_count[i] = 0; g_cursor[i] = 0; }
    if (i < NP) g_wsum[i] = 0.f;
}

// ---------------- K1: feat = h @ W_p via tf32 mma, fused el/er, fp16 store ----------------
__global__ void __launch_bounds__(256) k_gemm(const float* __restrict__ h,
                                              const float* __restrict__ W,
                                              const float* __restrict__ attn_l,
                                              const float* __restrict__ attn_r) {
    __shared__ float As[128 * 36];
    __shared__ float Ws[32 * 136];

    const int p = blockIdx.y;
    const int row0 = blockIdx.x * 128;
    const int tid = threadIdx.x;
    const int w = tid >> 5, lane = tid & 31;
    const int gid = lane >> 2, tig = lane & 3;
    const float* Wp = W + (size_t)p * INF * HD;

    float acc[16][4];
#pragma unroll
    for (int t = 0; t < 16; t++) { acc[t][0] = acc[t][1] = acc[t][2] = acc[t][3] = 0.f; }

    for (int kc = 0; kc < 4; kc++) {
        for (int i = tid; i < 1024; i += 256) {
            int r = i >> 3, q = i & 7;
            float4 v = make_float4(0.f, 0.f, 0.f, 0.f);
            if (row0 + r < NNODE)
                v = *(const float4*)(h + (size_t)(row0 + r) * INF + kc * 32 + q * 4);
            float4 o = make_float4(totf32(v.x), totf32(v.y), totf32(v.z), totf32(v.w));
            *(float4*)&As[r * 36 + q * 4] = o;
        }
        for (int i = tid; i < 1024; i += 256) {
            int r = i >> 5, q = i & 31;
            float4 v = *(const float4*)(Wp + (size_t)(kc * 32 + r) * HD + q * 4);
            float4 o = make_float4(totf32(v.x), totf32(v.y), totf32(v.z), totf32(v.w));
            *(float4*)&Ws[r * 136 + q * 4] = o;
        }
        __syncthreads();

#pragma unroll
        for (int ks = 0; ks < 4; ks++) {
            int kb = ks * 8;
            uint32_t a0 = __float_as_uint(As[(w * 16 + gid) * 36 + kb + tig]);
            uint32_t a1 = __float_as_uint(As[(w * 16 + gid + 8) * 36 + kb + tig]);
            uint32_t a2 = __float_as_uint(As[(w * 16 + gid) * 36 + kb + tig + 4]);
            uint32_t a3 = __float_as_uint(As[(w * 16 + gid + 8) * 36 + kb + tig + 4]);
#pragma unroll
            for (int nt = 0; nt < 16; nt++) {
                uint32_t b0 = __float_as_uint(Ws[(kb + tig) * 136 + nt * 8 + gid]);
                uint32_t b1 = __float_as_uint(Ws[(kb + tig + 4) * 136 + nt * 8 + gid]);
                mma8(acc[nt], a0, a1, a2, a3, b0, b1);
            }
        }
        __syncthreads();
    }

    const int r0 = row0 + w * 16 + gid;
    const int r1 = r0 + 8;
    const bool ok0 = r0 < NNODE, ok1 = r1 < NNODE;

#pragma unroll
    for (int nt = 0; nt < 16; nt++) {
        int c = nt * 8 + tig * 2;
        if (ok0) *(__half2*)&g_feat[((size_t)p * NNODE + r0) * HD + c] =
            __floats2half2_rn(acc[nt][0], acc[nt][1]);
        if (ok1) *(__half2*)&g_feat[((size_t)p * NNODE + r1) * HD + c] =
            __floats2half2_rn(acc[nt][2], acc[nt][3]);
    }

    const float* alp = attn_l + p * HD;
    const float* arp = attn_r + p * HD;
#pragma unroll
    for (int hd = 0; hd < 4; hd++) {
        float vl0 = 0.f, vl1 = 0.f, vr0 = 0.f, vr1 = 0.f;
#pragma unroll
        for (int t = 0; t < 4; t++) {
            int nt = hd * 4 + t;
            int c = nt * 8 + tig * 2;
            float w0 = alp[c], w1 = alp[c + 1];
            float u0 = arp[c], u1 = arp[c + 1];
            vl0 += acc[nt][0] * w0 + acc[nt][1] * w1;
            vl1 += acc[nt][2] * w0 + acc[nt][3] * w1;
            vr0 += acc[nt][0] * u0 + acc[nt][1] * u1;
            vr1 += acc[nt][2] * u0 + acc[nt][3] * u1;
        }
        vl0 += __shfl_xor_sync(0xffffffffu, vl0, 1); vl0 += __shfl_xor_sync(0xffffffffu, vl0, 2);
        vl1 += __shfl_xor_sync(0xffffffffu, vl1, 1); vl1 += __shfl_xor_sync(0xffffffffu, vl1, 2);
        vr0 += __shfl_xor_sync(0xffffffffu, vr0, 1); vr0 += __shfl_xor_sync(0xffffffffu, vr0, 2);
        vr1 += __shfl_xor_sync(0xffffffffu, vr1, 1); vr1 += __shfl_xor_sync(0xffffffffu, vr1, 2);
        if (tig == 0) {
            if (ok0) { g_el[(p * NNODE + r0) * NH + hd] = vl0;
                       g_er[(p * NNODE + r0) * NH + hd] = vr0; }
            if (ok1) { g_el[(p * NNODE + r1) * NH + hd] = vl1;
                       g_er[(p * NNODE + r1) * NH + hd] = vr1; }
        }
    }
}

// ---------------- K2: count in-degree ----------------
__global__ void k_count(const int* __restrict__ edge_dst) {
    int i = blockIdx.x * blockDim.x + threadIdx.x;
    if (i >= PE) return;
    int p = i / NE;
    atomicAdd(&g_count[p * NNODE + edge_dst[i]], 1);
}

// ---------------- scan (3 kernels) ----------------
__global__ void k_scan_blocks() {
    __shared__ int s[256];
    int base = blockIdx.x * SCAN_ITEMS;
    int t = threadIdx.x;
    int v = 0;
#pragma unroll
    for (int i = 0; i < 4; i++) {
        int idx = base + t * 4 + i;
        if (idx < PN) v += g_count[idx];
    }
    s[t] = v; __syncthreads();
    for (int o = 128; o > 0; o >>= 1) {
        if (t < o) s[t] += s[t + o];
        __syncthreads();
    }
    if (t == 0) g_bsums[blockIdx.x] = s[0];
}

__global__ void k_scan_bsums() {
    __shared__ int s[512];
    int t = threadIdx.x;
    int v = (t < NB) ? g_bsums[t] : 0;
    s[t] = v; __syncthreads();
    for (int o = 1; o < 512; o <<= 1) {
        int x = (t >= o) ? s[t - o] : 0;
        __syncthreads();
        s[t] += x;
        __syncthreads();
    }
    if (t < NB) g_bsums[t] = s[t] - v;  // exclusive
}

__global__ void k_scan_final() {
    __shared__ int s[256];
    int base = blockIdx.x * SCAN_ITEMS;
    int t = threadIdx.x;
    int loc[4]; int sum = 0;
#pragma unroll
    for (int i = 0; i < 4; i++) {
        int idx = base + t * 4 + i;
        loc[i] = (idx < PN) ? g_count[idx] : 0;
        sum += loc[i];
    }
    s[t] = sum; __syncthreads();
    for (int o = 1; o < 256; o <<= 1) {
        int x = (t >= o) ? s[t - o] : 0;
        __syncthreads();
        s[t] += x;
        __syncthreads();
    }
    int ex = s[t] - sum + g_bsums[blockIdx.x];
#pragma unroll
    for (int i = 0; i < 4; i++) {
        int idx = base + t * 4 + i;
        if (idx < PN) { g_off[idx] = ex; ex += loc[i]; }
    }
}

// ---------------- K3: scatter src by dst ----------------
__global__ void k_scatter(const int* __restrict__ edge_src,
                          const int* __restrict__ edge_dst) {
    int i = blockIdx.x * blockDim.x + threadIdx.x;
    if (i >= PE) return;
    int p = i / NE;
    int seg = p * NNODE + edge_dst[i];
    int pos = atomicAdd(&g_cursor[seg], 1);
    g_esrc[g_off[seg] + pos] = edge_src[i];
}

// ---------------- K4: fused GAT softmax + aggregate (warp per (p,node)) ----------------
__global__ void __launch_bounds__(256) k_p2(const float* __restrict__ bias) {
    int gw = (blockIdx.x * blockDim.x + threadIdx.x) >> 5;
    if (gw >= PN) return;
    const int lane = threadIdx.x & 31;
    const int p = gw / NNODE;
    const int start = g_off[gw];
    const int cnt = g_count[gw];
    const int hd = lane >> 3;   // head owning cols 4*lane..4*lane+3
    const float* elbase = g_el + (size_t)p * NNODE * NH;
    const __half* fb = g_feat + (size_t)p * NNODE * HD;
    const float4 er4 = *(const float4*)&g_er[gw * NH];

    float4 a = *(const float4*)&bias[p * HD + lane * 4];

    if (cnt > 0 && cnt <= 32) {
        // fast path: lane L owns edge L; everything register-resident
        int src = 0;
        float4 ex = make_float4(0.f, 0.f, 0.f, 0.f);
        if (lane < cnt) {
            src = g_esrc[start + lane];        // coalesced
            ex = edge_exp(elbase, src, er4);
        }
        float4 s = ex;
#pragma unroll
        for (int o = 16; o > 0; o >>= 1) {
            s.x += __shfl_xor_sync(0xffffffffu, s.x, o);
            s.y += __shfl_xor_sync(0xffffffffu, s.y, o);
            s.z += __shfl_xor_sync(0xffffffffu, s.z, o);
            s.w += __shfl_xor_sync(0xffffffffu, s.w, o);
        }
        float rs = 1.f / fmaxf(pick4(s, hd), 1e-9f);
        for (int j = 0; j < cnt; j++) {
            int sj = __shfl_sync(0xffffffffu, src, j);
            float4 exj = make_float4(__shfl_sync(0xffffffffu, ex.x, j),
                                     __shfl_sync(0xffffffffu, ex.y, j),
                                     __shfl_sync(0xffffffffu, ex.z, j),
                                     __shfl_sync(0xffffffffu, ex.w, j));
            float wgt = pick4(exj, hd) * rs;
            // 4 halves per lane: coalesced 256B/warp
            __half2 f01 = *(const __half2*)&fb[(size_t)sj * HD + lane * 4];
            __half2 f23 = *(const __half2*)&fb[(size_t)sj * HD + lane * 4 + 2];
            float2 g01 = __half22float2(f01);
            float2 g23 = __half22float2(f23);
            a.x += wgt * g01.x; a.y += wgt * g01.y;
            a.z += wgt * g23.x; a.w += wgt * g23.y;
        }
    } else if (cnt > 32) {
        // generic chunked path (rare)
        float4 s = make_float4(0.f, 0.f, 0.f, 0.f);
        for (int c0 = 0; c0 < cnt; c0 += 32) {
            if (c0 + lane < cnt) {
                int src = g_esrc[start + c0 + lane];
                float4 ex = edge_exp(elbase, src, er4);
                s.x += ex.x; s.y += ex.y; s.z += ex.z; s.w += ex.w;
            }
        }
#pragma unroll
        for (int o = 16; o > 0; o >>= 1) {
            s.x += __shfl_xor_sync(0xffffffffu, s.x, o);
            s.y += __shfl_xor_sync(0xffffffffu, s.y, o);
            s.z += __shfl_xor_sync(0xffffffffu, s.z, o);
            s.w += __shfl_xor_sync(0xffffffffu, s.w, o);
        }
        float rs = 1.f / fmaxf(pick4(s, hd), 1e-9f);
        for (int c0 = 0; c0 < cnt; c0 += 32) {
            int src = 0;
            float4 ex = make_float4(0.f, 0.f, 0.f, 0.f);
            if (c0 + lane < cnt) {
                src = g_esrc[start + c0 + lane];
                ex = edge_exp(elbase, src, er4);
            }
            int lim = min(32, cnt - c0);
            for (int j = 0; j < lim; j++) {
                int sj = __shfl_sync(0xffffffffu, src, j);
                float4 exj = make_float4(__shfl_sync(0xffffffffu, ex.x, j),
                                         __shfl_sync(0xffffffffu, ex.y, j),
                                         __shfl_sync(0xffffffffu, ex.z, j),
                                         __shfl_sync(0xffffffffu, ex.w, j));
                float wgt = pick4(exj, hd) * rs;
                __half2 f01 = *(const __half2*)&fb[(size_t)sj * HD + lane * 4];
                __half2 f23 = *(const __half2*)&fb[(size_t)sj * HD + lane * 4 + 2];
                float2 g01 = __half22float2(f01);
                float2 g23 = __half22float2(f23);
                a.x += wgt * g01.x; a.y += wgt * g01.y;
                a.z += wgt * g23.x; a.w += wgt * g23.y;
            }
        }
    }
    *(float4*)&g_z[(size_t)gw * HD + lane * 4] = a;
}

// ---------------- K5: semantic score via tf32 mma + fast tanh + full reduce ----------------
__global__ void __launch_bounds__(256) k_sem(const float* __restrict__ sa_w1,
                                             const float* __restrict__ sa_b1,
                                             const float* __restrict__ sa_w2) {
    __shared__ float Zs[128 * 36];
    __shared__ float W1s[32 * 72];
    __shared__ float s_sum;

    const int p = blockIdx.y;
    const int row0 = blockIdx.x * 128;
    const int tid = threadIdx.x;
    const int w = tid >> 5, lane = tid & 31;
    const int gid = lane >> 2, tig = lane & 3;
    if (tid == 0) s_sum = 0.f;

    float acc[8][4];
#pragma unroll
    for (int t = 0; t < 8; t++) { acc[t][0] = acc[t][1] = acc[t][2] = acc[t][3] = 0.f; }

    const float* zb = g_z + (size_t)p * NNODE * HD;
    for (int kc = 0; kc < 4; kc++) {
        for (int i = tid; i < 1024; i += 256) {
            int r = i >> 3, q = i & 7;
            float4 v = make_float4(0.f, 0.f, 0.f, 0.f);
            if (row0 + r < NNODE)
                v = *(const float4*)(zb + (size_t)(row0 + r) * HD + kc * 32 + q * 4);
            float4 o = make_float4(totf32(v.x), totf32(v.y), totf32(v.z), totf32(v.w));
            *(float4*)&Zs[r * 36 + q * 4] = o;
        }
        for (int i = tid; i < 512; i += 256) {
            int r = i >> 4, q = i & 15;
            float4 v = *(const float4*)(sa_w1 + (size_t)(kc * 32 + r) * HID + q * 4);
            float4 o = make_float4(totf32(v.x), totf32(v.y), totf32(v.z), totf32(v.w));
            *(float4*)&W1s[r * 72 + q * 4] = o;
        }
        __syncthreads();

#pragma unroll
        for (int ks = 0; ks < 4; ks++) {
            int kb = ks * 8;
            uint32_t a0 = __float_as_uint(Zs[(w * 16 + gid) * 36 + kb + tig]);
            uint32_t a1 = __float_as_uint(Zs[(w * 16 + gid + 8) * 36 + kb + tig]);
            uint32_t a2 = __float_as_uint(Zs[(w * 16 + gid) * 36 + kb + tig + 4]);
            uint32_t a3 = __float_as_uint(Zs[(w * 16 + gid + 8) * 36 + kb + tig + 4]);
#pragma unroll
            for (int nt = 0; nt < 8; nt++) {
                uint32_t b0 = __float_as_uint(W1s[(kb + tig) * 72 + nt * 8 + gid]);
                uint32_t b1 = __float_as_uint(W1s[(kb + tig + 4) * 72 + nt * 8 + gid]);
                mma8(acc[nt], a0, a1, a2, a3, b0, b1);
            }
        }
        __syncthreads();
    }

    const int r0 = row0 + w * 16 + gid;
    const int r1 = r0 + 8;
    const float m0 = (r0 < NNODE) ? 1.f : 0.f;
    const float m1 = (r1 < NNODE) ? 1.f : 0.f;

    float part = 0.f;
#pragma unroll
    for (int nt = 0; nt < 8; nt++) {
        int c = nt * 8 + tig * 2;
        float bb0 = sa_b1[c], bb1 = sa_b1[c + 1];
        float w20 = sa_w2[c], w21 = sa_w2[c + 1];
        part += m0 * (tanhfast(acc[nt][0] + bb0) * w20 + tanhfast(acc[nt][1] + bb1) * w21);
        part += m1 * (tanhfast(acc[nt][2] + bb0) * w20 + tanhfast(acc[nt][3] + bb1) * w21);
    }
#pragma unroll
    for (int o = 16; o > 0; o >>= 1) part += __shfl_xor_sync(0xffffffffu, part, o);
    if (lane == 0) atomicAdd(&s_sum, part);
    __syncthreads();
    if (tid == 0) atomicAdd(&g_wsum[p], s_sum);
}

// ---------------- K6: final weighted sum ----------------
__global__ void k_final(float* __restrict__ out) {
    int idx = blockIdx.x * blockDim.x + threadIdx.x;
    if (idx >= NNODE * HD) return;
    float w0 = g_wsum[0] * (1.f / NNODE);
    float w1 = g_wsum[1] * (1.f / NNODE);
    float w2 = g_wsum[2] * (1.f / NNODE);
    float mx = fmaxf(w0, fmaxf(w1, w2));
    float b0 = __expf(w0 - mx), b1 = __expf(w1 - mx), b2 = __expf(w2 - mx);
    float inv = 1.f / (b0 + b1 + b2);
    out[idx] = (b0 * g_z[idx] +
                b1 * g_z[(size_t)NNODE * HD + idx] +
                b2 * g_z[(size_t)2 * NNODE * HD + idx]) * inv;
}

// ---------------- launch ----------------
extern "C" void kernel_launch(void* const* d_in, const int* in_sizes, int n_in,
                              void* d_out, int out_size) {
    const float* h    = (const float*)d_in[0];
    const int*   esrc = (const int*)d_in[1];
    const int*   edst = (const int*)d_in[2];
    const float* W    = (const float*)d_in[3];
    const float* al   = (const float*)d_in[4];
    const float* ar   = (const float*)d_in[5];
    const float* bias = (const float*)d_in[6];
    const float* w1   = (const float*)d_in[7];
    const float* b1   = (const float*)d_in[8];
    const float* w2   = (const float*)d_in[9];
    float* out = (float*)d_out;

    // k_gemm at launch index 3 so the ncu window catches it (gemm is
    // independent of the CSR chain, so this order is dependency-safe).
    k_init<<<(PN + 255) / 256, 256>>>();
    k_count<<<(PE + 255) / 256, 256>>>(edst);
    k_scan_blocks<<<NB, 256>>>();
    k_gemm<<<dim3(MBLK, NP), 256>>>(h, W, al, ar);
    k_scan_bsums<<<1, 512>>>();
    k_scan_final<<<NB, 256>>>();
    k_scatter<<<(PE + 255) / 256, 256>>>(esrc, edst);
    k_p2<<<PN / 8, 256>>>(bias);
    k_sem<<<dim3(MBLK, NP), 256>>>(w1, b1, w2);
    k_final<<<(NNODE * HD + 255) / 256, 256>>>(out);
}

// round 7
// speedup vs baseline: 2.9403x; 1.1175x over previous
#include <cuda_runtime.h>
#include <cuda_fp16.h>
#include <math.h>
#include <stdint.h>

#define NNODE 100000
#define NP 3
#define NE 800000
#define INF 128
#define NH 4
#define HD 128
#define HID 64
#define PN (NP*NNODE)
#define PE (NP*NE)
#define NEG_SLOPE 0.2f

#define SCAN_ITEMS 1024
#define NB ((PN + SCAN_ITEMS - 1) / SCAN_ITEMS)   // 293
#define MBLK ((NNODE + 127) / 128)                // 782

// ---------------- device scratch (static, no allocations) ----------------
__device__ __align__(16) __half g_feat[(size_t)NP * NNODE * HD];
__device__ __align__(16) float g_z[(size_t)NP * NNODE * HD];
__device__ __align__(16) float g_htf[(size_t)NNODE * INF];   // tf32-rounded h
__device__ __align__(16) float g_Wtf[NP * INF * HD];         // tf32-rounded W
__device__ __align__(16) float g_el[PN * NH];
__device__ __align__(16) float g_er[PN * NH];
__device__ int   g_count[PN];
__device__ int   g_cursor[PN];
__device__ int   g_off[PN];
__device__ int   g_bsums[512];
__device__ int   g_esrc[PE];
__device__ float g_wsum[NP];

// ---------------- helpers ----------------
__device__ __forceinline__ float totf32(float x) {
    uint32_t u; asm("cvt.rna.tf32.f32 %0, %1;" : "=r"(u) : "f"(x));
    return __uint_as_float(u);
}
__device__ __forceinline__ void mma8(float* d, uint32_t a0, uint32_t a1,
                                     uint32_t a2, uint32_t a3,
                                     uint32_t b0, uint32_t b1) {
    asm("mma.sync.aligned.m16n8k8.row.col.f32.tf32.tf32.f32 "
        "{%0,%1,%2,%3},{%4,%5,%6,%7},{%8,%9},{%0,%1,%2,%3};"
        : "+f"(d[0]), "+f"(d[1]), "+f"(d[2]), "+f"(d[3])
        : "r"(a0), "r"(a1), "r"(a2), "r"(a3), "r"(b0), "r"(b1));
}
__device__ __forceinline__ void cpa16(uint32_t dst, const void* src) {
    asm volatile("cp.async.cg.shared.global [%0], [%1], 16;" :: "r"(dst), "l"(src));
}
__device__ __forceinline__ void cpa_commit_wait() {
    asm volatile("cp.async.commit_group;");
    asm volatile("cp.async.wait_group 0;" ::: "memory");
}
__device__ __forceinline__ float tanhfast(float x) {
    float y; asm("tanh.approx.f32 %0, %1;" : "=f"(y) : "f"(x)); return y;
}
__device__ __forceinline__ float pick4(float4 v, int h) {
    float r = v.x;
    r = (h == 1) ? v.y : r;
    r = (h == 2) ? v.z : r;
    r = (h == 3) ? v.w : r;
    return r;
}
__device__ __forceinline__ float lrelu(float e) {
    return fmaxf(e, NEG_SLOPE * e);
}
__device__ __forceinline__ float4 edge_exp(const float* __restrict__ elbase,
                                           int src, float4 er4) {
    float4 el4 = *(const float4*)&elbase[src * NH];
    return make_float4(__expf(lrelu(el4.x + er4.x)),
                       __expf(lrelu(el4.y + er4.y)),
                       __expf(lrelu(el4.z + er4.z)),
                       __expf(lrelu(el4.w + er4.w)));
}

// ---------------- K_cvt: h,W -> tf32-rounded copies ----------------
#define H4 (NNODE * INF / 4)          // 3,200,000
#define W4 (NP * INF * HD / 4)        // 12,288
__global__ void k_cvt(const float* __restrict__ h, const float* __restrict__ W) {
    int i = blockIdx.x * blockDim.x + threadIdx.x;
    if (i < H4) {
        float4 v = ((const float4*)h)[i];
        ((float4*)g_htf)[i] = make_float4(totf32(v.x), totf32(v.y), totf32(v.z), totf32(v.w));
    } else if (i < H4 + W4) {
        int j = i - H4;
        float4 v = ((const float4*)W)[j];
        ((float4*)g_Wtf)[j] = make_float4(totf32(v.x), totf32(v.y), totf32(v.z), totf32(v.w));
    }
}

// ---------------- K0: init ----------------
__global__ void k_init() {
    int i = blockIdx.x * blockDim.x + threadIdx.x;
    if (i < PN) { g_count[i] = 0; g_cursor[i] = 0; }
    if (i < NP) g_wsum[i] = 0.f;
}

// ---------------- K1: feat = h @ W_p via tf32 mma, cp.async staging ----------------
__global__ void __launch_bounds__(256, 3) k_gemm(const float* __restrict__ attn_l,
                                                 const float* __restrict__ attn_r) {
    __shared__ float As[128 * 36];
    __shared__ float Ws[32 * 136];

    const int p = blockIdx.y;
    const int row0 = blockIdx.x * 128;
    const int tid = threadIdx.x;
    const int w = tid >> 5, lane = tid & 31;
    const int gid = lane >> 2, tig = lane & 3;
    const float* Wp = g_Wtf + (size_t)p * INF * HD;
    const uint32_t As_u = (uint32_t)__cvta_generic_to_shared(As);
    const uint32_t Ws_u = (uint32_t)__cvta_generic_to_shared(Ws);

    float acc[16][4];
#pragma unroll
    for (int t = 0; t < 16; t++) { acc[t][0] = acc[t][1] = acc[t][2] = acc[t][3] = 0.f; }

    for (int kc = 0; kc < 4; kc++) {
        // A: rows row0..+127 (clamped; out-of-range rows give discarded garbage)
        for (int i = tid; i < 1024; i += 256) {
            int r = i >> 3, q = i & 7;
            int row = min(row0 + r, NNODE - 1);
            cpa16(As_u + (uint32_t)(r * 36 + q * 4) * 4,
                  g_htf + (size_t)row * INF + kc * 32 + q * 4);
        }
        // B: W rows kc*32..+31, all 128 cols
        for (int i = tid; i < 1024; i += 256) {
            int r = i >> 5, q = i & 31;
            cpa16(Ws_u + (uint32_t)(r * 136 + q * 4) * 4,
                  Wp + (size_t)(kc * 32 + r) * HD + q * 4);
        }
        cpa_commit_wait();
        __syncthreads();

#pragma unroll
        for (int ks = 0; ks < 4; ks++) {
            int kb = ks * 8;
            uint32_t a0 = __float_as_uint(As[(w * 16 + gid) * 36 + kb + tig]);
            uint32_t a1 = __float_as_uint(As[(w * 16 + gid + 8) * 36 + kb + tig]);
            uint32_t a2 = __float_as_uint(As[(w * 16 + gid) * 36 + kb + tig + 4]);
            uint32_t a3 = __float_as_uint(As[(w * 16 + gid + 8) * 36 + kb + tig + 4]);
#pragma unroll
            for (int nt = 0; nt < 16; nt++) {
                uint32_t b0 = __float_as_uint(Ws[(kb + tig) * 136 + nt * 8 + gid]);
                uint32_t b1 = __float_as_uint(Ws[(kb + tig + 4) * 136 + nt * 8 + gid]);
                mma8(acc[nt], a0, a1, a2, a3, b0, b1);
            }
        }
        __syncthreads();
    }

    const int r0 = row0 + w * 16 + gid;
    const int r1 = r0 + 8;
    const bool ok0 = r0 < NNODE, ok1 = r1 < NNODE;

#pragma unroll
    for (int nt = 0; nt < 16; nt++) {
        int c = nt * 8 + tig * 2;
        if (ok0) *(__half2*)&g_feat[((size_t)p * NNODE + r0) * HD + c] =
            __floats2half2_rn(acc[nt][0], acc[nt][1]);
        if (ok1) *(__half2*)&g_feat[((size_t)p * NNODE + r1) * HD + c] =
            __floats2half2_rn(acc[nt][2], acc[nt][3]);
    }

    const float* alp = attn_l + p * HD;
    const float* arp = attn_r + p * HD;
#pragma unroll
    for (int hd = 0; hd < 4; hd++) {
        float vl0 = 0.f, vl1 = 0.f, vr0 = 0.f, vr1 = 0.f;
#pragma unroll
        for (int t = 0; t < 4; t++) {
            int nt = hd * 4 + t;
            int c = nt * 8 + tig * 2;
            float w0 = alp[c], w1 = alp[c + 1];
            float u0 = arp[c], u1 = arp[c + 1];
            vl0 += acc[nt][0] * w0 + acc[nt][1] * w1;
            vl1 += acc[nt][2] * w0 + acc[nt][3] * w1;
            vr0 += acc[nt][0] * u0 + acc[nt][1] * u1;
            vr1 += acc[nt][2] * u0 + acc[nt][3] * u1;
        }
        vl0 += __shfl_xor_sync(0xffffffffu, vl0, 1); vl0 += __shfl_xor_sync(0xffffffffu, vl0, 2);
        vl1 += __shfl_xor_sync(0xffffffffu, vl1, 1); vl1 += __shfl_xor_sync(0xffffffffu, vl1, 2);
        vr0 += __shfl_xor_sync(0xffffffffu, vr0, 1); vr0 += __shfl_xor_sync(0xffffffffu, vr0, 2);
        vr1 += __shfl_xor_sync(0xffffffffu, vr1, 1); vr1 += __shfl_xor_sync(0xffffffffu, vr1, 2);
        if (tig == 0) {
            if (ok0) { g_el[(p * NNODE + r0) * NH + hd] = vl0;
                       g_er[(p * NNODE + r0) * NH + hd] = vr0; }
            if (ok1) { g_el[(p * NNODE + r1) * NH + hd] = vl1;
                       g_er[(p * NNODE + r1) * NH + hd] = vr1; }
        }
    }
}

// ---------------- K2: count in-degree ----------------
__global__ void k_count(const int* __restrict__ edge_dst) {
    int i = blockIdx.x * blockDim.x + threadIdx.x;
    if (i >= PE) return;
    int p = i / NE;
    atomicAdd(&g_count[p * NNODE + edge_dst[i]], 1);
}

// ---------------- scan (3 kernels) ----------------
__global__ void k_scan_blocks() {
    __shared__ int s[256];
    int base = blockIdx.x * SCAN_ITEMS;
    int t = threadIdx.x;
    int v = 0;
#pragma unroll
    for (int i = 0; i < 4; i++) {
        int idx = base + t * 4 + i;
        if (idx < PN) v += g_count[idx];
    }
    s[t] = v; __syncthreads();
    for (int o = 128; o > 0; o >>= 1) {
        if (t < o) s[t] += s[t + o];
        __syncthreads();
    }
    if (t == 0) g_bsums[blockIdx.x] = s[0];
}

__global__ void k_scan_bsums() {
    __shared__ int s[512];
    int t = threadIdx.x;
    int v = (t < NB) ? g_bsums[t] : 0;
    s[t] = v; __syncthreads();
    for (int o = 1; o < 512; o <<= 1) {
        int x = (t >= o) ? s[t - o] : 0;
        __syncthreads();
        s[t] += x;
        __syncthreads();
    }
    if (t < NB) g_bsums[t] = s[t] - v;  // exclusive
}

__global__ void k_scan_final() {
    __shared__ int s[256];
    int base = blockIdx.x * SCAN_ITEMS;
    int t = threadIdx.x;
    int loc[4]; int sum = 0;
#pragma unroll
    for (int i = 0; i < 4; i++) {
        int idx = base + t * 4 + i;
        loc[i] = (idx < PN) ? g_count[idx] : 0;
        sum += loc[i];
    }
    s[t] = sum; __syncthreads();
    for (int o = 1; o < 256; o <<= 1) {
        int x = (t >= o) ? s[t - o] : 0;
        __syncthreads();
        s[t] += x;
        __syncthreads();
    }
    int ex = s[t] - sum + g_bsums[blockIdx.x];
#pragma unroll
    for (int i = 0; i < 4; i++) {
        int idx = base + t * 4 + i;
        if (idx < PN) { g_off[idx] = ex; ex += loc[i]; }
    }
}

// ---------------- K3: scatter src by dst ----------------
__global__ void k_scatter(const int* __restrict__ edge_src,
                          const int* __restrict__ edge_dst) {
    int i = blockIdx.x * blockDim.x + threadIdx.x;
    if (i >= PE) return;
    int p = i / NE;
    int seg = p * NNODE + edge_dst[i];
    int pos = atomicAdd(&g_cursor[seg], 1);
    g_esrc[g_off[seg] + pos] = edge_src[i];
}

// ---------------- K4: fused GAT softmax + aggregate ----------------
__global__ void __launch_bounds__(256) k_p2(const float* __restrict__ bias) {
    int gw = (blockIdx.x * blockDim.x + threadIdx.x) >> 5;
    if (gw >= PN) return;
    const int lane = threadIdx.x & 31;
    const int p = gw / NNODE;
    const int start = g_off[gw];
    const int cnt = g_count[gw];
    const int hd = lane >> 3;
    const float* elbase = g_el + (size_t)p * NNODE * NH;
    const __half* fb = g_feat + (size_t)p * NNODE * HD;
    const float4 er4 = *(const float4*)&g_er[gw * NH];

    float4 a = *(const float4*)&bias[p * HD + lane * 4];

    if (cnt > 0 && cnt <= 32) {
        int src = 0;
        float4 ex = make_float4(0.f, 0.f, 0.f, 0.f);
        if (lane < cnt) {
            src = g_esrc[start + lane];
            ex = edge_exp(elbase, src, er4);
        }
        float4 s = ex;
#pragma unroll
        for (int o = 16; o > 0; o >>= 1) {
            s.x += __shfl_xor_sync(0xffffffffu, s.x, o);
            s.y += __shfl_xor_sync(0xffffffffu, s.y, o);
            s.z += __shfl_xor_sync(0xffffffffu, s.z, o);
            s.w += __shfl_xor_sync(0xffffffffu, s.w, o);
        }
        float rs = 1.f / fmaxf(pick4(s, hd), 1e-9f);
        for (int j = 0; j < cnt; j++) {
            int sj = __shfl_sync(0xffffffffu, src, j);
            float4 exj = make_float4(__shfl_sync(0xffffffffu, ex.x, j),
                                     __shfl_sync(0xffffffffu, ex.y, j),
                                     __shfl_sync(0xffffffffu, ex.z, j),
                                     __shfl_sync(0xffffffffu, ex.w, j));
            float wgt = pick4(exj, hd) * rs;
            __half2 f01 = *(const __half2*)&fb[(size_t)sj * HD + lane * 4];
            __half2 f23 = *(const __half2*)&fb[(size_t)sj * HD + lane * 4 + 2];
            float2 g01 = __half22float2(f01);
            float2 g23 = __half22float2(f23);
            a.x += wgt * g01.x; a.y += wgt * g01.y;
            a.z += wgt * g23.x; a.w += wgt * g23.y;
        }
    } else if (cnt > 32) {
        float4 s = make_float4(0.f, 0.f, 0.f, 0.f);
        for (int c0 = 0; c0 < cnt; c0 += 32) {
            if (c0 + lane < cnt) {
                int src = g_esrc[start + c0 + lane];
                float4 ex = edge_exp(elbase, src, er4);
                s.x += ex.x; s.y += ex.y; s.z += ex.z; s.w += ex.w;
            }
        }
#pragma unroll
        for (int o = 16; o > 0; o >>= 1) {
            s.x += __shfl_xor_sync(0xffffffffu, s.x, o);
            s.y += __shfl_xor_sync(0xffffffffu, s.y, o);
            s.z += __shfl_xor_sync(0xffffffffu, s.z, o);
            s.w += __shfl_xor_sync(0xffffffffu, s.w, o);
        }
        float rs = 1.f / fmaxf(pick4(s, hd), 1e-9f);
        for (int c0 = 0; c0 < cnt; c0 += 32) {
            int src = 0;
            float4 ex = make_float4(0.f, 0.f, 0.f, 0.f);
            if (c0 + lane < cnt) {
                src = g_esrc[start + c0 + lane];
                ex = edge_exp(elbase, src, er4);
            }
            int lim = min(32, cnt - c0);
            for (int j = 0; j < lim; j++) {
                int sj = __shfl_sync(0xffffffffu, src, j);
                float4 exj = make_float4(__shfl_sync(0xffffffffu, ex.x, j),
                                         __shfl_sync(0xffffffffu, ex.y, j),
                                         __shfl_sync(0xffffffffu, ex.z, j),
                                         __shfl_sync(0xffffffffu, ex.w, j));
                float wgt = pick4(exj, hd) * rs;
                __half2 f01 = *(const __half2*)&fb[(size_t)sj * HD + lane * 4];
                __half2 f23 = *(const __half2*)&fb[(size_t)sj * HD + lane * 4 + 2];
                float2 g01 = __half22float2(f01);
                float2 g23 = __half22float2(f23);
                a.x += wgt * g01.x; a.y += wgt * g01.y;
                a.z += wgt * g23.x; a.w += wgt * g23.y;
            }
        }
    }
    *(float4*)&g_z[(size_t)gw * HD + lane * 4] = a;
}

// ---------------- K5: semantic score via tf32 mma ----------------
__global__ void __launch_bounds__(256) k_sem(const float* __restrict__ sa_w1,
                                             const float* __restrict__ sa_b1,
                                             const float* __restrict__ sa_w2) {
    __shared__ float Zs[128 * 36];
    __shared__ float W1s[32 * 72];
    __shared__ float s_sum;

    const int p = blockIdx.y;
    const int row0 = blockIdx.x * 128;
    const int tid = threadIdx.x;
    const int w = tid >> 5, lane = tid & 31;
    const int gid = lane >> 2, tig = lane & 3;
    if (tid == 0) s_sum = 0.f;

    float acc[8][4];
#pragma unroll
    for (int t = 0; t < 8; t++) { acc[t][0] = acc[t][1] = acc[t][2] = acc[t][3] = 0.f; }

    const float* zb = g_z + (size_t)p * NNODE * HD;
    for (int kc = 0; kc < 4; kc++) {
        for (int i = tid; i < 1024; i += 256) {
            int r = i >> 3, q = i & 7;
            float4 v = make_float4(0.f, 0.f, 0.f, 0.f);
            if (row0 + r < NNODE)
                v = *(const float4*)(zb + (size_t)(row0 + r) * HD + kc * 32 + q * 4);
            float4 o = make_float4(totf32(v.x), totf32(v.y), totf32(v.z), totf32(v.w));
            *(float4*)&Zs[r * 36 + q * 4] = o;
        }
        for (int i = tid; i < 512; i += 256) {
            int r = i >> 4, q = i & 15;
            float4 v = *(const float4*)(sa_w1 + (size_t)(kc * 32 + r) * HID + q * 4);
            float4 o = make_float4(totf32(v.x), totf32(v.y), totf32(v.z), totf32(v.w));
            *(float4*)&W1s[r * 72 + q * 4] = o;
        }
        __syncthreads();

#pragma unroll
        for (int ks = 0; ks < 4; ks++) {
            int kb = ks * 8;
            uint32_t a0 = __float_as_uint(Zs[(w * 16 + gid) * 36 + kb + tig]);
            uint32_t a1 = __float_as_uint(Zs[(w * 16 + gid + 8) * 36 + kb + tig]);
            uint32_t a2 = __float_as_uint(Zs[(w * 16 + gid) * 36 + kb + tig + 4]);
            uint32_t a3 = __float_as_uint(Zs[(w * 16 + gid + 8) * 36 + kb + tig + 4]);
#pragma unroll
            for (int nt = 0; nt < 8; nt++) {
                uint32_t b0 = __float_as_uint(W1s[(kb + tig) * 72 + nt * 8 + gid]);
                uint32_t b1 = __float_as_uint(W1s[(kb + tig + 4) * 72 + nt * 8 + gid]);
                mma8(acc[nt], a0, a1, a2, a3, b0, b1);
            }
        }
        __syncthreads();
    }

    const int r0 = row0 + w * 16 + gid;
    const int r1 = r0 + 8;
    const float m0 = (r0 < NNODE) ? 1.f : 0.f;
    const float m1 = (r1 < NNODE) ? 1.f : 0.f;

    float part = 0.f;
#pragma unroll
    for (int nt = 0; nt < 8; nt++) {
        int c = nt * 8 + tig * 2;
        float bb0 = sa_b1[c], bb1 = sa_b1[c + 1];
        float w20 = sa_w2[c], w21 = sa_w2[c + 1];
        part += m0 * (tanhfast(acc[nt][0] + bb0) * w20 + tanhfast(acc[nt][1] + bb1) * w21);
        part += m1 * (tanhfast(acc[nt][2] + bb0) * w20 + tanhfast(acc[nt][3] + bb1) * w21);
    }
#pragma unroll
    for (int o = 16; o > 0; o >>= 1) part += __shfl_xor_sync(0xffffffffu, part, o);
    if (lane == 0) atomicAdd(&s_sum, part);
    __syncthreads();
    if (tid == 0) atomicAdd(&g_wsum[p], s_sum);
}

// ---------------- K6: final weighted sum ----------------
__global__ void k_final(float* __restrict__ out) {
    int idx = blockIdx.x * blockDim.x + threadIdx.x;
    if (idx >= NNODE * HD) return;
    float w0 = g_wsum[0] * (1.f / NNODE);
    float w1 = g_wsum[1] * (1.f / NNODE);
    float w2 = g_wsum[2] * (1.f / NNODE);
    float mx = fmaxf(w0, fmaxf(w1, w2));
    float b0 = __expf(w0 - mx), b1 = __expf(w1 - mx), b2 = __expf(w2 - mx);
    float inv = 1.f / (b0 + b1 + b2);
    out[idx] = (b0 * g_z[idx] +
                b1 * g_z[(size_t)NNODE * HD + idx] +
                b2 * g_z[(size_t)2 * NNODE * HD + idx]) * inv;
}

// ---------------- launch ----------------
extern "C" void kernel_launch(void* const* d_in, const int* in_sizes, int n_in,
                              void* d_out, int out_size) {
    const float* h    = (const float*)d_in[0];
    const int*   esrc = (const int*)d_in[1];
    const int*   edst = (const int*)d_in[2];
    const float* W    = (const float*)d_in[3];
    const float* al   = (const float*)d_in[4];
    const float* ar   = (const float*)d_in[5];
    const float* bias = (const float*)d_in[6];
    const float* w1   = (const float*)d_in[7];
    const float* b1   = (const float*)d_in[8];
    const float* w2   = (const float*)d_in[9];
    float* out = (float*)d_out;

    // lazily created side stream + events (first call is the uncaptured
    // correctness run; later captured calls reuse the same handles)
    static cudaStream_t s2 = nullptr;
    static cudaEvent_t ev_fork = nullptr, ev_join = nullptr;
    if (s2 == nullptr) {
        cudaStreamCreateWithFlags(&s2, cudaStreamNonBlocking);
        cudaEventCreateWithFlags(&ev_fork, cudaEventDisableTiming);
        cudaEventCreateWithFlags(&ev_join, cudaEventDisableTiming);
    }

    // fork: CSR chain on s2 concurrent with cvt+gemm on the main stream
    cudaEventRecord(ev_fork, 0);
    cudaStreamWaitEvent(s2, ev_fork, 0);

    k_init<<<(PN + 255) / 256, 256, 0, s2>>>();
    k_count<<<(PE + 255) / 256, 256, 0, s2>>>(edst);
    k_scan_blocks<<<NB, 256, 0, s2>>>();
    k_scan_bsums<<<1, 512, 0, s2>>>();
    k_scan_final<<<NB, 256, 0, s2>>>();
    k_scatter<<<(PE + 255) / 256, 256, 0, s2>>>(esrc, edst);
    cudaEventRecord(ev_join, s2);

    k_cvt<<<(H4 + W4 + 255) / 256, 256>>>(h, W);
    k_gemm<<<dim3(MBLK, NP), 256>>>(al, ar);

    // join
    cudaStreamWaitEvent(0, ev_join, 0);

    k_p2<<<PN / 8, 256>>>(bias);
    k_sem<<<dim3(MBLK, NP), 256>>>(w1, b1, w2);
    k_final<<<(NNODE * HD + 255) / 256, 256>>>(out);
}

// round 8
// speedup vs baseline: 3.0498x; 1.0372x over previous
#include <cuda_runtime.h>
#include <cuda_fp16.h>
#include <math.h>
#include <stdint.h>

#define NNODE 100000
#define NP 3
#define NE 800000
#define INF 128
#define NH 4
#define HD 128
#define HID 64
#define PN (NP*NNODE)
#define PE (NP*NE)
#define NEG_SLOPE 0.2f

#define SCAN_ITEMS 1024
#define NB ((PN + SCAN_ITEMS - 1) / SCAN_ITEMS)   // 293
#define MBLK ((NNODE + 127) / 128)                // 782

// gemm dynamic smem: A 128x132 f32 + B 32x136 f32
#define GEMM_SMEM ((128 * 132 + 32 * 136) * 4)    // 84992 B

// ---------------- device scratch (static, no allocations) ----------------
__device__ __align__(16) __half g_feat[(size_t)NP * NNODE * HD];
__device__ __align__(16) __half g_zh[(size_t)NP * NNODE * HD];   // fp16 GAT outputs
__device__ __align__(16) float g_el[PN * NH];
__device__ __align__(16) float g_er[PN * NH];
__device__ int   g_count[PN];
__device__ int   g_cursor[PN];
__device__ int   g_off[PN];
__device__ int   g_bsums[512];
__device__ int   g_esrc[PE];
__device__ float g_wsum[NP];

// ---------------- helpers ----------------
__device__ __forceinline__ float totf32(float x) {
    uint32_t u; asm("cvt.rna.tf32.f32 %0, %1;" : "=r"(u) : "f"(x));
    return __uint_as_float(u);
}
__device__ __forceinline__ float4 totf32_4(float4 v) {
    return make_float4(totf32(v.x), totf32(v.y), totf32(v.z), totf32(v.w));
}
__device__ __forceinline__ void mma8(float* d, uint32_t a0, uint32_t a1,
                                     uint32_t a2, uint32_t a3,
                                     uint32_t b0, uint32_t b1) {
    asm("mma.sync.aligned.m16n8k8.row.col.f32.tf32.tf32.f32 "
        "{%0,%1,%2,%3},{%4,%5,%6,%7},{%8,%9},{%0,%1,%2,%3};"
        : "+f"(d[0]), "+f"(d[1]), "+f"(d[2]), "+f"(d[3])
        : "r"(a0), "r"(a1), "r"(a2), "r"(a3), "r"(b0), "r"(b1));
}
__device__ __forceinline__ float tanhfast(float x) {
    float y; asm("tanh.approx.f32 %0, %1;" : "=f"(y) : "f"(x)); return y;
}
__device__ __forceinline__ float pick4(float4 v, int h) {
    float r = v.x;
    r = (h == 1) ? v.y : r;
    r = (h == 2) ? v.z : r;
    r = (h == 3) ? v.w : r;
    return r;
}
__device__ __forceinline__ float lrelu(float e) {
    return fmaxf(e, NEG_SLOPE * e);
}
__device__ __forceinline__ float4 edge_exp(const float* __restrict__ elbase,
                                           int src, float4 er4) {
    float4 el4 = *(const float4*)&elbase[src * NH];
    return make_float4(__expf(lrelu(el4.x + er4.x)),
                       __expf(lrelu(el4.y + er4.y)),
                       __expf(lrelu(el4.z + er4.z)),
                       __expf(lrelu(el4.w + er4.w)));
}

// ---------------- K0: init ----------------
__global__ void k_init() {
    int i = blockIdx.x * blockDim.x + threadIdx.x;
    if (i < PN) { g_count[i] = 0; g_cursor[i] = 0; }
    if (i < NP) g_wsum[i] = 0.f;
}

// ---------------- K1: feat = h @ W_p, A-resident, loops p in-kernel ----------------
__global__ void __launch_bounds__(256, 2) k_gemm(const float* __restrict__ h,
                                                 const float* __restrict__ W,
                                                 const float* __restrict__ attn_l,
                                                 const float* __restrict__ attn_r) {
    extern __shared__ float sm[];
    float* As = sm;                 // 128 x 132 (full K resident, tf32 bits)
    float* Bs = sm + 128 * 132;     // 32 x 136 (one K-chunk of W_p)

    const int row0 = blockIdx.x * 128;
    const int tid = threadIdx.x;
    const int w = tid >> 5, lane = tid & 31;
    const int gid = lane >> 2, tig = lane & 3;

    // stage full A tile once, converting raw h -> tf32
    for (int i = tid; i < 4096; i += 256) {
        int r = i >> 5, q = i & 31;
        int row = min(row0 + r, NNODE - 1);   // clamp; garbage rows discarded
        float4 v = *(const float4*)(h + (size_t)row * INF + q * 4);
        *(float4*)&As[r * 132 + q * 4] = totf32_4(v);
    }
    __syncthreads();

    const int r0 = row0 + w * 16 + gid;
    const int r1 = r0 + 8;
    const bool ok0 = r0 < NNODE, ok1 = r1 < NNODE;

    for (int p = 0; p < NP; p++) {
        float acc[16][4];
#pragma unroll
        for (int t = 0; t < 16; t++) { acc[t][0] = acc[t][1] = acc[t][2] = acc[t][3] = 0.f; }

        const float* Wp = W + (size_t)p * INF * HD;
        for (int kc = 0; kc < 4; kc++) {
            for (int i = tid; i < 1024; i += 256) {
                int r = i >> 5, q = i & 31;
                float4 v = *(const float4*)(Wp + (size_t)(kc * 32 + r) * HD + q * 4);
                *(float4*)&Bs[r * 136 + q * 4] = totf32_4(v);
            }
            __syncthreads();

#pragma unroll
            for (int ks = 0; ks < 4; ks++) {
                int ka = kc * 32 + ks * 8;   // offset into resident A
                int kb = ks * 8;             // offset into B chunk
                uint32_t a0 = __float_as_uint(As[(w * 16 + gid) * 132 + ka + tig]);
                uint32_t a1 = __float_as_uint(As[(w * 16 + gid + 8) * 132 + ka + tig]);
                uint32_t a2 = __float_as_uint(As[(w * 16 + gid) * 132 + ka + tig + 4]);
                uint32_t a3 = __float_as_uint(As[(w * 16 + gid + 8) * 132 + ka + tig + 4]);
#pragma unroll
                for (int nt = 0; nt < 16; nt++) {
                    uint32_t b0 = __float_as_uint(Bs[(kb + tig) * 136 + nt * 8 + gid]);
                    uint32_t b1 = __float_as_uint(Bs[(kb + tig + 4) * 136 + nt * 8 + gid]);
                    mma8(acc[nt], a0, a1, a2, a3, b0, b1);
                }
            }
            __syncthreads();
        }

        // epilogue for this p: fp16 feat store + el/er reduction
#pragma unroll
        for (int nt = 0; nt < 16; nt++) {
            int c = nt * 8 + tig * 2;
            if (ok0) *(__half2*)&g_feat[((size_t)p * NNODE + r0) * HD + c] =
                __floats2half2_rn(acc[nt][0], acc[nt][1]);
            if (ok1) *(__half2*)&g_feat[((size_t)p * NNODE + r1) * HD + c] =
                __floats2half2_rn(acc[nt][2], acc[nt][3]);
        }

        const float* alp = attn_l + p * HD;
        const float* arp = attn_r + p * HD;
#pragma unroll
        for (int hd = 0; hd < 4; hd++) {
            float vl0 = 0.f, vl1 = 0.f, vr0 = 0.f, vr1 = 0.f;
#pragma unroll
            for (int t = 0; t < 4; t++) {
                int nt = hd * 4 + t;
                int c = nt * 8 + tig * 2;
                float w0 = alp[c], w1 = alp[c + 1];
                float u0 = arp[c], u1 = arp[c + 1];
                vl0 += acc[nt][0] * w0 + acc[nt][1] * w1;
                vl1 += acc[nt][2] * w0 + acc[nt][3] * w1;
                vr0 += acc[nt][0] * u0 + acc[nt][1] * u1;
                vr1 += acc[nt][2] * u0 + acc[nt][3] * u1;
            }
            vl0 += __shfl_xor_sync(0xffffffffu, vl0, 1); vl0 += __shfl_xor_sync(0xffffffffu, vl0, 2);
            vl1 += __shfl_xor_sync(0xffffffffu, vl1, 1); vl1 += __shfl_xor_sync(0xffffffffu, vl1, 2);
            vr0 += __shfl_xor_sync(0xffffffffu, vr0, 1); vr0 += __shfl_xor_sync(0xffffffffu, vr0, 2);
            vr1 += __shfl_xor_sync(0xffffffffu, vr1, 1); vr1 += __shfl_xor_sync(0xffffffffu, vr1, 2);
            if (tig == 0) {
                if (ok0) { g_el[(p * NNODE + r0) * NH + hd] = vl0;
                           g_er[(p * NNODE + r0) * NH + hd] = vr0; }
                if (ok1) { g_el[(p * NNODE + r1) * NH + hd] = vl1;
                           g_er[(p * NNODE + r1) * NH + hd] = vr1; }
            }
        }
    }
}

// ---------------- K2: count in-degree ----------------
__global__ void k_count(const int* __restrict__ edge_dst) {
    int i = blockIdx.x * blockDim.x + threadIdx.x;
    if (i >= PE) return;
    int p = i / NE;
    atomicAdd(&g_count[p * NNODE + edge_dst[i]], 1);
}

// ---------------- scan (3 kernels) ----------------
__global__ void k_scan_blocks() {
    __shared__ int s[256];
    int base = blockIdx.x * SCAN_ITEMS;
    int t = threadIdx.x;
    int v = 0;
#pragma unroll
    for (int i = 0; i < 4; i++) {
        int idx = base + t * 4 + i;
        if (idx < PN) v += g_count[idx];
    }
    s[t] = v; __syncthreads();
    for (int o = 128; o > 0; o >>= 1) {
        if (t < o) s[t] += s[t + o];
        __syncthreads();
    }
    if (t == 0) g_bsums[blockIdx.x] = s[0];
}

__global__ void k_scan_bsums() {
    __shared__ int s[512];
    int t = threadIdx.x;
    int v = (t < NB) ? g_bsums[t] : 0;
    s[t] = v; __syncthreads();
    for (int o = 1; o < 512; o <<= 1) {
        int x = (t >= o) ? s[t - o] : 0;
        __syncthreads();
        s[t] += x;
        __syncthreads();
    }
    if (t < NB) g_bsums[t] = s[t] - v;  // exclusive
}

__global__ void k_scan_final() {
    __shared__ int s[256];
    int base = blockIdx.x * SCAN_ITEMS;
    int t = threadIdx.x;
    int loc[4]; int sum = 0;
#pragma unroll
    for (int i = 0; i < 4; i++) {
        int idx = base + t * 4 + i;
        loc[i] = (idx < PN) ? g_count[idx] : 0;
        sum += loc[i];
    }
    s[t] = sum; __syncthreads();
    for (int o = 1; o < 256; o <<= 1) {
        int x = (t >= o) ? s[t - o] : 0;
        __syncthreads();
        s[t] += x;
        __syncthreads();
    }
    int ex = s[t] - sum + g_bsums[blockIdx.x];
#pragma unroll
    for (int i = 0; i < 4; i++) {
        int idx = base + t * 4 + i;
        if (idx < PN) { g_off[idx] = ex; ex += loc[i]; }
    }
}

// ---------------- K3: scatter src by dst ----------------
__global__ void k_scatter(const int* __restrict__ edge_src,
                          const int* __restrict__ edge_dst) {
    int i = blockIdx.x * blockDim.x + threadIdx.x;
    if (i >= PE) return;
    int p = i / NE;
    int seg = p * NNODE + edge_dst[i];
    int pos = atomicAdd(&g_cursor[seg], 1);
    g_esrc[g_off[seg] + pos] = edge_src[i];
}

// ---------------- K4: fused GAT softmax + aggregate ----------------
__global__ void __launch_bounds__(256) k_p2(const float* __restrict__ bias) {
    int gw = (blockIdx.x * blockDim.x + threadIdx.x) >> 5;
    if (gw >= PN) return;
    const int lane = threadIdx.x & 31;
    const int p = gw / NNODE;
    const int start = g_off[gw];
    const int cnt = g_count[gw];
    const int hd = lane >> 3;
    const float* elbase = g_el + (size_t)p * NNODE * NH;
    const __half* fb = g_feat + (size_t)p * NNODE * HD;
    const float4 er4 = *(const float4*)&g_er[gw * NH];

    float4 a = *(const float4*)&bias[p * HD + lane * 4];

    if (cnt > 0 && cnt <= 32) {
        int src = 0;
        float4 ex = make_float4(0.f, 0.f, 0.f, 0.f);
        if (lane < cnt) {
            src = g_esrc[start + lane];
            ex = edge_exp(elbase, src, er4);
        }
        float4 s = ex;
#pragma unroll
        for (int o = 16; o > 0; o >>= 1) {
            s.x += __shfl_xor_sync(0xffffffffu, s.x, o);
            s.y += __shfl_xor_sync(0xffffffffu, s.y, o);
            s.z += __shfl_xor_sync(0xffffffffu, s.z, o);
            s.w += __shfl_xor_sync(0xffffffffu, s.w, o);
        }
        float rs = 1.f / fmaxf(pick4(s, hd), 1e-9f);
        for (int j = 0; j < cnt; j++) {
            int sj = __shfl_sync(0xffffffffu, src, j);
            float4 exj = make_float4(__shfl_sync(0xffffffffu, ex.x, j),
                                     __shfl_sync(0xffffffffu, ex.y, j),
                                     __shfl_sync(0xffffffffu, ex.z, j),
                                     __shfl_sync(0xffffffffu, ex.w, j));
            float wgt = pick4(exj, hd) * rs;
            uint2 fv = *(const uint2*)&fb[(size_t)sj * HD + lane * 4];
            float2 g01 = __half22float2(*(__half2*)&fv.x);
            float2 g23 = __half22float2(*(__half2*)&fv.y);
            a.x += wgt * g01.x; a.y += wgt * g01.y;
            a.z += wgt * g23.x; a.w += wgt * g23.y;
        }
    } else if (cnt > 32) {
        float4 s = make_float4(0.f, 0.f, 0.f, 0.f);
        for (int c0 = 0; c0 < cnt; c0 += 32) {
            if (c0 + lane < cnt) {
                int src = g_esrc[start + c0 + lane];
                float4 ex = edge_exp(elbase, src, er4);
                s.x += ex.x; s.y += ex.y; s.z += ex.z; s.w += ex.w;
            }
        }
#pragma unroll
        for (int o = 16; o > 0; o >>= 1) {
            s.x += __shfl_xor_sync(0xffffffffu, s.x, o);
            s.y += __shfl_xor_sync(0xffffffffu, s.y, o);
            s.z += __shfl_xor_sync(0xffffffffu, s.z, o);
            s.w += __shfl_xor_sync(0xffffffffu, s.w, o);
        }
        float rs = 1.f / fmaxf(pick4(s, hd), 1e-9f);
        for (int c0 = 0; c0 < cnt; c0 += 32) {
            int src = 0;
            float4 ex = make_float4(0.f, 0.f, 0.f, 0.f);
            if (c0 + lane < cnt) {
                src = g_esrc[start + c0 + lane];
                ex = edge_exp(elbase, src, er4);
            }
            int lim = min(32, cnt - c0);
            for (int j = 0; j < lim; j++) {
                int sj = __shfl_sync(0xffffffffu, src, j);
                float4 exj = make_float4(__shfl_sync(0xffffffffu, ex.x, j),
                                         __shfl_sync(0xffffffffu, ex.y, j),
                                         __shfl_sync(0xffffffffu, ex.z, j),
                                         __shfl_sync(0xffffffffu, ex.w, j));
                float wgt = pick4(exj, hd) * rs;
                uint2 fv = *(const uint2*)&fb[(size_t)sj * HD + lane * 4];
                float2 g01 = __half22float2(*(__half2*)&fv.x);
                float2 g23 = __half22float2(*(__half2*)&fv.y);
                a.x += wgt * g01.x; a.y += wgt * g01.y;
                a.z += wgt * g23.x; a.w += wgt * g23.y;
            }
        }
    }
    // fp16 z store (2x uint2)
    __half2 z01 = __floats2half2_rn(a.x, a.y);
    __half2 z23 = __floats2half2_rn(a.z, a.w);
    uint2 zv;
    zv.x = *(uint32_t*)&z01;
    zv.y = *(uint32_t*)&z23;
    *(uint2*)&g_zh[(size_t)gw * HD + lane * 4] = zv;
}

// ---------------- K5: semantic score via tf32 mma (reads fp16 z) ----------------
__global__ void __launch_bounds__(256) k_sem(const float* __restrict__ sa_w1,
                                             const float* __restrict__ sa_b1,
                                             const float* __restrict__ sa_w2) {
    __shared__ float Zs[128 * 36];
    __shared__ float W1s[32 * 72];
    __shared__ float s_sum;

    const int p = blockIdx.y;
    const int row0 = blockIdx.x * 128;
    const int tid = threadIdx.x;
    const int w = tid >> 5, lane = tid & 31;
    const int gid = lane >> 2, tig = lane & 3;
    if (tid == 0) s_sum = 0.f;

    float acc[8][4];
#pragma unroll
    for (int t = 0; t < 8; t++) { acc[t][0] = acc[t][1] = acc[t][2] = acc[t][3] = 0.f; }

    const __half* zb = g_zh + (size_t)p * NNODE * HD;
    for (int kc = 0; kc < 4; kc++) {
        // stage z chunk: 128 rows x 32 cols, from half
        for (int i = tid; i < 1024; i += 256) {
            int r = i >> 3, q = i & 7;   // q indexes 4-col group
            float4 o = make_float4(0.f, 0.f, 0.f, 0.f);
            if (row0 + r < NNODE) {
                uint2 hv = *(const uint2*)(zb + (size_t)(row0 + r) * HD + kc * 32 + q * 4);
                float2 f01 = __half22float2(*(__half2*)&hv.x);
                float2 f23 = __half22float2(*(__half2*)&hv.y);
                o = make_float4(totf32(f01.x), totf32(f01.y), totf32(f23.x), totf32(f23.y));
            }
            *(float4*)&Zs[r * 36 + q * 4] = o;
        }
        for (int i = tid; i < 512; i += 256) {
            int r = i >> 4, q = i & 15;
            float4 v = *(const float4*)(sa_w1 + (size_t)(kc * 32 + r) * HID + q * 4);
            *(float4*)&W1s[r * 72 + q * 4] = totf32_4(v);
        }
        __syncthreads();

#pragma unroll
        for (int ks = 0; ks < 4; ks++) {
            int kb = ks * 8;
            uint32_t a0 = __float_as_uint(Zs[(w * 16 + gid) * 36 + kb + tig]);
            uint32_t a1 = __float_as_uint(Zs[(w * 16 + gid + 8) * 36 + kb + tig]);
            uint32_t a2 = __float_as_uint(Zs[(w * 16 + gid) * 36 + kb + tig + 4]);
            uint32_t a3 = __float_as_uint(Zs[(w * 16 + gid + 8) * 36 + kb + tig + 4]);
#pragma unroll
            for (int nt = 0; nt < 8; nt++) {
                uint32_t b0 = __float_as_uint(W1s[(kb + tig) * 72 + nt * 8 + gid]);
                uint32_t b1 = __float_as_uint(W1s[(kb + tig + 4) * 72 + nt * 8 + gid]);
                mma8(acc[nt], a0, a1, a2, a3, b0, b1);
            }
        }
        __syncthreads();
    }

    const int r0 = row0 + w * 16 + gid;
    const int r1 = r0 + 8;
    const float m0 = (r0 < NNODE) ? 1.f : 0.f;
    const float m1 = (r1 < NNODE) ? 1.f : 0.f;

    float part = 0.f;
#pragma unroll
    for (int nt = 0; nt < 8; nt++) {
        int c = nt * 8 + tig * 2;
        float bb0 = sa_b1[c], bb1 = sa_b1[c + 1];
        float w20 = sa_w2[c], w21 = sa_w2[c + 1];
        part += m0 * (tanhfast(acc[nt][0] + bb0) * w20 + tanhfast(acc[nt][1] + bb1) * w21);
        part += m1 * (tanhfast(acc[nt][2] + bb0) * w20 + tanhfast(acc[nt][3] + bb1) * w21);
    }
#pragma unroll
    for (int o = 16; o > 0; o >>= 1) part += __shfl_xor_sync(0xffffffffu, part, o);
    if (lane == 0) atomicAdd(&s_sum, part);
    __syncthreads();
    if (tid == 0) atomicAdd(&g_wsum[p], s_sum);
}

// ---------------- K6: final weighted sum (2 elems/thread) ----------------
__global__ void k_final(float* __restrict__ out) {
    int i2 = blockIdx.x * blockDim.x + threadIdx.x;
    if (i2 >= NNODE * HD / 2) return;
    float w0 = g_wsum[0] * (1.f / NNODE);
    float w1 = g_wsum[1] * (1.f / NNODE);
    float w2 = g_wsum[2] * (1.f / NNODE);
    float mx = fmaxf(w0, fmaxf(w1, w2));
    float b0 = __expf(w0 - mx), b1 = __expf(w1 - mx), b2 = __expf(w2 - mx);
    float inv = 1.f / (b0 + b1 + b2);
    b0 *= inv; b1 *= inv; b2 *= inv;
    size_t idx = (size_t)i2 * 2;
    float2 z0 = __half22float2(*(const __half2*)&g_zh[idx]);
    float2 z1 = __half22float2(*(const __half2*)&g_zh[(size_t)NNODE * HD + idx]);
    float2 z2 = __half22float2(*(const __half2*)&g_zh[(size_t)2 * NNODE * HD + idx]);
    float2 o;
    o.x = b0 * z0.x + b1 * z1.x + b2 * z2.x;
    o.y = b0 * z0.y + b1 * z1.y + b2 * z2.y;
    *(float2*)&out[idx] = o;
}

// ---------------- launch ----------------
extern "C" void kernel_launch(void* const* d_in, const int* in_sizes, int n_in,
                              void* d_out, int out_size) {
    const float* h    = (const float*)d_in[0];
    const int*   esrc = (const int*)d_in[1];
    const int*   edst = (const int*)d_in[2];
    const float* W    = (const float*)d_in[3];
    const float* al   = (const float*)d_in[4];
    const float* ar   = (const float*)d_in[5];
    const float* bias = (const float*)d_in[6];
    const float* w1   = (const float*)d_in[7];
    const float* b1   = (const float*)d_in[8];
    const float* w2   = (const float*)d_in[9];
    float* out = (float*)d_out;

    static cudaStream_t s2 = nullptr;
    static cudaEvent_t ev_fork = nullptr, ev_join = nullptr;
    if (s2 == nullptr) {
        cudaStreamCreateWithFlags(&s2, cudaStreamNonBlocking);
        cudaEventCreateWithFlags(&ev_fork, cudaEventDisableTiming);
        cudaEventCreateWithFlags(&ev_join, cudaEventDisableTiming);
        cudaFuncSetAttribute(k_gemm, cudaFuncAttributeMaxDynamicSharedMemorySize, GEMM_SMEM);
    }

    // fork: CSR chain on s2 concurrent with gemm on the main stream
    cudaEventRecord(ev_fork, 0);
    cudaStreamWaitEvent(s2, ev_fork, 0);

    k_init<<<(PN + 255) / 256, 256, 0, s2>>>();
    k_count<<<(PE + 255) / 256, 256, 0, s2>>>(edst);
    k_scan_blocks<<<NB, 256, 0, s2>>>();
    k_scan_bsums<<<1, 512, 0, s2>>>();
    k_scan_final<<<NB, 256, 0, s2>>>();
    k_scatter<<<(PE + 255) / 256, 256, 0, s2>>>(esrc, edst);
    cudaEventRecord(ev_join, s2);

    k_gemm<<<MBLK, 256, GEMM_SMEM>>>(h, W, al, ar);

    // join
    cudaStreamWaitEvent(0, ev_join, 0);

    k_p2<<<PN / 8, 256>>>(bias);
    k_sem<<<dim3(MBLK, NP), 256>>>(w1, b1, w2);
    k_final<<<(NNODE * HD / 2 + 255) / 256, 256>>>(out);
}